// round 1
// baseline (speedup 1.0000x reference)
#include <cuda_runtime.h>
#include <math.h>

#define N_NODES 16384
#define N_EDGES 262144
#define NT      5
#define FIN     75
#define TGD     375     /* T*F_IN */
#define ABW     750     /* A(375)+B(375) per node */
#define NLAYERS 4
#define NGRAPH  256
#define LOG17F  2.8332133440562162f
#define BN_EPS  1e-5f
#define STD_EPS 1e-5f

// ---------------- scratch (static device globals; no allocation) -------------
__device__ float g_h[N_NODES * FIN];
__device__ float g_AB[N_NODES * ABW];       // A at [n*750 + 0..374], B at [+375..749]
__device__ float g_agg[N_NODES * 1500];     // (n, t, 4*75): mean|mn|mx|std per tower
__device__ float g_amp[N_NODES * 2];        // amp, 1/amp
__device__ int   g_cnt[N_NODES];
__device__ int   g_rowptr[N_NODES + 1];
__device__ int   g_wp[N_NODES];
__device__ int   g_col[N_EDGES];            // src | (attr<<20)
__device__ float g_Ce[4 * TGD];             // per-attr message table (incl. pre_b)
__device__ float g_bnsum[FIN];
__device__ float g_bnsq[FIN];
__device__ float g_graph[NGRAPH * FIN];

// ---------------- init: zero degree counts + graph accumulator ---------------
__global__ void k_init() {
    int idx = blockIdx.x * blockDim.x + threadIdx.x;
    if (idx < N_NODES) g_cnt[idx] = 0;
    if (idx < NGRAPH * FIN) g_graph[idx] = 0.0f;
}

// ---------------- CSR build --------------------------------------------------
__global__ void k_count(const int* __restrict__ ei) {
    int e = blockIdx.x * blockDim.x + threadIdx.x;
    if (e < N_EDGES) atomicAdd(&g_cnt[ei[N_EDGES + e]], 1);
}

__global__ void k_scan() {
    __shared__ int part[256];
    int tid = threadIdx.x;
    int base = tid * 64;
    int s = 0;
    for (int i = 0; i < 64; i++) s += g_cnt[base + i];
    part[tid] = s;
    __syncthreads();
    if (tid == 0) {
        int acc = 0;
        for (int i = 0; i < 256; i++) { int v = part[i]; part[i] = acc; acc += v; }
        g_rowptr[N_NODES] = N_EDGES;
    }
    __syncthreads();
    int acc = part[tid];
    for (int i = 0; i < 64; i++) {
        int n = base + i;
        g_rowptr[n] = acc;
        g_wp[n] = acc;
        acc += g_cnt[n];
    }
}

__global__ void k_scatter(const int* __restrict__ ei, const int* __restrict__ ea) {
    int e = blockIdx.x * blockDim.x + threadIdx.x;
    if (e < N_EDGES) {
        int src = ei[e];
        int dst = ei[N_EDGES + e];
        int a = ea[e];
        int pos = atomicAdd(&g_wp[dst], 1);
        g_col[pos] = src | (a << 20);
    }
}

// ---------------- node embedding ---------------------------------------------
__global__ void k_embed(const int* __restrict__ x, const float* __restrict__ emb) {
    int idx = blockIdx.x * blockDim.x + threadIdx.x;
    if (idx < N_NODES * FIN) {
        int n = idx / FIN, f = idx % FIN;
        g_h[idx] = emb[x[n] * FIN + f];
    }
}

// ---------------- per-layer: edge message table Ce (4 x 375), + zero BN sums -
__global__ void k_ce(int l, const float* __restrict__ edge_emb,
                     const float* __restrict__ encw, const float* __restrict__ encb,
                     const float* __restrict__ prew, const float* __restrict__ preb) {
    __shared__ float EE[4 * FIN];
    int tid = threadIdx.x;
    for (int idx = tid; idx < 4 * FIN; idx += blockDim.x) {
        int a = idx / FIN, f = idx % FIN;
        float v = encb[l * FIN + f];
        for (int d = 0; d < 50; d++)
            v += edge_emb[a * 50 + d] * encw[(l * 50 + d) * FIN + f];
        EE[idx] = v;
    }
    if (tid < FIN) { g_bnsum[tid] = 0.0f; g_bnsq[tid] = 0.0f; }
    __syncthreads();
    for (int idx = tid; idx < 4 * TGD; idx += blockDim.x) {
        int a = idx / TGD, tg = idx % TGD;
        int t = tg / FIN, g = tg % FIN;
        float v = preb[(l * NT + t) * FIN + g];
        const float* We = prew + ((size_t)(l * NT + t) * 225 + 150) * FIN + g;
        for (int f = 0; f < FIN; f++)
            v += EE[a * FIN + f] * We[f * FIN];
        g_Ce[idx] = v;
    }
}

// ---------------- per-layer: AB = h @ [Wi | Wj]  (N x 750) -------------------
// block: 32 nodes, 256 threads. tile the 750 output dims by 125.
__global__ void __launch_bounds__(256) k_ab(int l, const float* __restrict__ prew) {
    __shared__ float hs[32 * FIN];
    __shared__ float wt[75 * 128];   // tile stride 125, padded alloc for OOB-safe reads
    int tid = threadIdx.x;
    int nb = blockIdx.x * 32;
    for (int idx = tid; idx < 32 * FIN; idx += 256)
        hs[idx] = g_h[nb * FIN + idx];

    int j = tid & 7;
    int nloc = tid >> 3;
    const size_t lw_base = (size_t)l * NT * 225 * FIN;

    for (int gt = 0; gt < ABW; gt += 125) {
        __syncthreads();
        for (int idx = tid; idx < 75 * 125; idx += 256) {
            int f = idx / 125, gg = idx % 125;
            int G = gt + gg;
            int t, g, fo;
            if (G < TGD) { t = G / FIN; g = G % FIN; fo = 0; }
            else         { int Gp = G - TGD; t = Gp / FIN; g = Gp % FIN; fo = FIN; }
            wt[f * 125 + gg] = prew[lw_base + ((size_t)t * 225 + fo + f) * FIN + g];
        }
        __syncthreads();
        float acc[16];
#pragma unroll
        for (int k = 0; k < 16; k++) acc[k] = 0.0f;
        for (int f = 0; f < FIN; f++) {
            float hv = hs[nloc * FIN + f];
            const float* w = &wt[f * 125 + j];
#pragma unroll
            for (int k = 0; k < 16; k++) acc[k] += hv * w[8 * k];   // padded: safe
        }
        float* out = g_AB + (size_t)(nb + nloc) * ABW + gt;
#pragma unroll
        for (int k = 0; k < 16; k++) {
            int g = j + 8 * k;
            if (g < 125) out[g] = acc[k];
        }
    }
}

// ---------------- per-layer: aggregation (sum/sumsq/min/max over dst) --------
// block: 4 nodes x 128 threads; each thread handles dims d0, d0+128, d0+256.
__global__ void __launch_bounds__(512) k_agg() {
    __shared__ float sCe[4 * TGD];
    int tid = threadIdx.x;
    for (int idx = tid; idx < 4 * TGD; idx += 512) sCe[idx] = g_Ce[idx];
    __syncthreads();

    int grp = tid >> 7;
    int d0 = tid & 127;
    int n = blockIdx.x * 4 + grp;
    int r0 = g_rowptr[n], r1 = g_rowptr[n + 1];
    int cnt = r1 - r0;

    float s0 = 0, s1 = 0, s2 = 0;
    float q0 = 0, q1 = 0, q2 = 0;
    float mn0 = 3.4e38f, mn1 = 3.4e38f, mn2 = 3.4e38f;
    float mx0 = -3.4e38f, mx1 = -3.4e38f, mx2 = -3.4e38f;
    const int d1 = d0 + 128, d2 = d0 + 256;
    const bool v2ok = (d2 < TGD);

    for (int i = r0; i < r1; i++) {
        int c = g_col[i];
        int src = c & 0xFFFFF;
        int a = c >> 20;
        const float* B = g_AB + (size_t)src * ABW + TGD;
        const float* C = sCe + a * TGD;
        float v0 = B[d0] + C[d0];
        float v1 = B[d1] + C[d1];
        s0 += v0; q0 += v0 * v0; mn0 = fminf(mn0, v0); mx0 = fmaxf(mx0, v0);
        s1 += v1; q1 += v1 * v1; mn1 = fminf(mn1, v1); mx1 = fmaxf(mx1, v1);
        if (v2ok) {
            float v2 = B[d2] + C[d2];
            s2 += v2; q2 += v2 * v2; mn2 = fminf(mn2, v2); mx2 = fmaxf(mx2, v2);
        }
    }

    float fc = cnt > 0 ? (float)cnt : 1.0f;
    float amp = logf(fc + 1.0f) / LOG17F;
    if (d0 == 0) { g_amp[2 * n] = amp; g_amp[2 * n + 1] = 1.0f / amp; }

    float inv = 1.0f / fc;
    float ss[3] = { s0, s1, s2 };
    float qq[3] = { q0, q1, q2 };
    float mns[3] = { mn0, mn1, mn2 };
    float mxs[3] = { mx0, mx1, mx2 };
#pragma unroll
    for (int r = 0; r < 3; r++) {
        int d = d0 + 128 * r;
        if (d >= TGD) break;
        float mean, mnv, mxv, stdv;
        if (cnt > 0) {
            float Ai = g_AB[(size_t)n * ABW + d];
            float m1 = ss[r] * inv;
            float m2 = qq[r] * inv;
            float var = m2 - m1 * m1;
            var = fmaxf(var, 0.0f);
            stdv = sqrtf(var + STD_EPS);
            mean = Ai + m1;
            mnv = Ai + mns[r];
            mxv = Ai + mxs[r];
        } else {
            mean = 0.0f; mnv = 0.0f; mxv = 0.0f; stdv = sqrtf(STD_EPS);
        }
        int t = d / FIN, g = d % FIN;
        float* o = g_agg + (size_t)n * 1500 + t * 300 + g;
        o[0] = mean; o[75] = mnv; o[150] = mxv; o[225] = stdv;
    }
}

// ---------------- per-layer: post towers + lin + BN-stat accumulation --------
// block: 8 nodes, 256 threads.
__global__ void __launch_bounds__(256) k_post(int l,
        const float* __restrict__ postw, const float* __restrict__ postb,
        const float* __restrict__ linw, const float* __restrict__ linb) {
    __shared__ float sLw[FIN * FIN];
    __shared__ float sPost[8 * FIN];
    __shared__ float sAmp[16];
    __shared__ float sB[2 * FIN];
    int tid = threadIdx.x;
    int nb = blockIdx.x * 8;

    for (int idx = tid; idx < FIN * FIN; idx += 256)
        sLw[idx] = linw[l * FIN * FIN + idx];
    if (tid < 16) sAmp[tid] = g_amp[nb * 2 + tid];
    if (tid < 2 * FIN) sB[tid] = 0.0f;
    __syncthreads();

    // post: for each (node s, out o): post = qb + sum_d agg[d]*(q1 + amp*q2 + inv*q3)
    for (int idx = tid; idx < 8 * FIN; idx += 256) {
        int s = idx / FIN, o = idx % FIN;
        int t = o / 15, oo = o % 15;
        const float* qw = postw + (size_t)(l * NT + t) * 900 * 15 + oo;
        float amp = sAmp[2 * s], inv = sAmp[2 * s + 1];
        float acc = postb[(l * NT + t) * 15 + oo];
        const float* a = g_agg + (size_t)(nb + s) * 1500 + t * 300;
#pragma unroll 4
        for (int d = 0; d < 300; d++) {
            float w = __ldg(&qw[d * 15])
                    + amp * __ldg(&qw[(300 + d) * 15])
                    + inv * __ldg(&qw[(600 + d) * 15]);
            acc += __ldg(&a[d]) * w;
        }
        sPost[idx] = acc;
    }
    __syncthreads();

    // lin (75x75) + BN partial sums
    for (int idx = tid; idx < 8 * FIN; idx += 256) {
        int s = idx / FIN, g = idx % FIN;
        float acc = linb[l * FIN + g];
        const float* p = sPost + s * FIN;
#pragma unroll 5
        for (int k = 0; k < FIN; k++) acc += p[k] * sLw[k * FIN + g];
        g_h[(size_t)(nb + s) * FIN + g] = acc;
        atomicAdd(&sB[g], acc);
        atomicAdd(&sB[FIN + g], acc * acc);
    }
    __syncthreads();
    if (tid < FIN) {
        atomicAdd(&g_bnsum[tid], sB[tid]);
        atomicAdd(&g_bnsq[tid], sB[FIN + tid]);
    }
}

// ---------------- per-layer: BN apply + ReLU ---------------------------------
__global__ void k_bn(int l, const float* __restrict__ gamma, const float* __restrict__ beta) {
    __shared__ float sc[FIN], bi[FIN];
    int tid = threadIdx.x;
    if (tid < FIN) {
        float mu = g_bnsum[tid] * (1.0f / N_NODES);
        float var = g_bnsq[tid] * (1.0f / N_NODES) - mu * mu;
        float s = gamma[l * FIN + tid] * rsqrtf(var + BN_EPS);
        sc[tid] = s;
        bi[tid] = beta[l * FIN + tid] - mu * s;
    }
    __syncthreads();
    int idx = blockIdx.x * blockDim.x + tid;
    if (idx < N_NODES * FIN) {
        int g = idx % FIN;
        float v = g_h[idx] * sc[g] + bi[g];
        g_h[idx] = fmaxf(v, 0.0f);
    }
}

// ---------------- readout: segment sum over graphs ---------------------------
__global__ void k_readout(const int* __restrict__ batch) {
    int idx = blockIdx.x * blockDim.x + threadIdx.x;
    if (idx < N_NODES * FIN) {
        int n = idx / FIN, g = idx % FIN;
        atomicAdd(&g_graph[batch[n] * FIN + g], g_h[idx]);
    }
}

// ---------------- final MLP --------------------------------------------------
__global__ void k_mlp(const float* __restrict__ w1, const float* __restrict__ b1,
                      const float* __restrict__ w2, const float* __restrict__ b2,
                      const float* __restrict__ w3, const float* __restrict__ b3,
                      float* __restrict__ out) {
    __shared__ float row[FIN], t1[50], t2[25];
    int b = blockIdx.x, tid = threadIdx.x;
    if (tid < FIN) row[tid] = g_graph[b * FIN + tid];
    __syncthreads();
    if (tid < 50) {
        float a = b1[tid];
        for (int f = 0; f < FIN; f++) a += row[f] * w1[f * 50 + tid];
        t1[tid] = fmaxf(a, 0.0f);
    }
    __syncthreads();
    if (tid < 25) {
        float a = b2[tid];
        for (int f = 0; f < 50; f++) a += t1[f] * w2[f * 25 + tid];
        t2[tid] = fmaxf(a, 0.0f);
    }
    __syncthreads();
    if (tid == 0) {
        float a = b3[0];
        for (int f = 0; f < 25; f++) a += t2[f] * w3[f];
        out[b] = a;
    }
}

// ---------------- launch -----------------------------------------------------
extern "C" void kernel_launch(void* const* d_in, const int* in_sizes, int n_in,
                              void* d_out, int out_size) {
    const int*   x        = (const int*)d_in[0];
    const int*   ei       = (const int*)d_in[1];
    const int*   ea       = (const int*)d_in[2];
    const int*   batch    = (const int*)d_in[3];
    const float* node_emb = (const float*)d_in[4];
    const float* edge_emb = (const float*)d_in[5];
    const float* encw     = (const float*)d_in[6];
    const float* encb     = (const float*)d_in[7];
    const float* prew     = (const float*)d_in[8];
    const float* preb     = (const float*)d_in[9];
    const float* postw    = (const float*)d_in[10];
    const float* postb    = (const float*)d_in[11];
    const float* linw     = (const float*)d_in[12];
    const float* linb     = (const float*)d_in[13];
    const float* gamma    = (const float*)d_in[14];
    const float* beta     = (const float*)d_in[15];
    const float* w1       = (const float*)d_in[16];
    const float* b1       = (const float*)d_in[17];
    const float* w2       = (const float*)d_in[18];
    const float* b2       = (const float*)d_in[19];
    const float* w3       = (const float*)d_in[20];
    const float* b3       = (const float*)d_in[21];
    float* out = (float*)d_out;

    k_init<<<(NGRAPH * FIN + 255) / 256, 256>>>();
    k_count<<<N_EDGES / 256, 256>>>(ei);
    k_scan<<<1, 256>>>();
    k_scatter<<<N_EDGES / 256, 256>>>(ei, ea);
    k_embed<<<(N_NODES * FIN + 255) / 256, 256>>>(x, node_emb);

    for (int l = 0; l < NLAYERS; l++) {
        k_ce<<<1, 512>>>(l, edge_emb, encw, encb, prew, preb);
        k_ab<<<N_NODES / 32, 256>>>(l, prew);
        k_agg<<<N_NODES / 4, 512>>>();
        k_post<<<N_NODES / 8, 256>>>(l, postw, postb, linw, linb);
        k_bn<<<(N_NODES * FIN + 255) / 256, 256>>>(l, gamma, beta);
    }

    k_readout<<<(N_NODES * FIN + 255) / 256, 256>>>(batch);
    k_mlp<<<NGRAPH, 96>>>(w1, b1, w2, b2, w3, b3, out);
}

// round 3
// speedup vs baseline: 1.6470x; 1.6470x over previous
#include <cuda_runtime.h>
#include <math.h>

#define N_NODES 16384
#define N_EDGES 262144
#define NT      5
#define FIN     75
#define TGD     375     /* T*F_IN */
#define ABW     750     /* A(375)+B(375) per node */
#define NLAYERS 4
#define NGRAPH  256
#define LOG17F  2.8332133440562162f
#define BN_EPS  1e-5f
#define STD_EPS 1e-5f

// ---------------- scratch (static device globals; no allocation) -------------
__device__ float g_h[N_NODES * FIN];
__device__ float g_AB[N_NODES * ABW];       // A at [n*750 + 0..374], B at [+375..749]
__device__ float g_agg[N_NODES * 1500];     // (n, t, 4*75): mean|mn|mx|std per tower
__device__ float g_amp[N_NODES * 2];        // amp, 1/amp
__device__ int   g_cnt[N_NODES];
__device__ int   g_rowptr[N_NODES + 1];
__device__ int   g_wp[N_NODES];
__device__ int   g_col[N_EDGES];            // src | (attr<<20)
__device__ float g_Ce[4 * TGD];             // per-attr message table (incl. pre_b)
__device__ float g_bnsum[FIN];
__device__ float g_bnsq[FIN];
__device__ float g_graph[NGRAPH * FIN];

// ---------------- init: zero degree counts + graph accumulator ---------------
__global__ void k_init() {
    int idx = blockIdx.x * blockDim.x + threadIdx.x;
    if (idx < N_NODES) g_cnt[idx] = 0;
    if (idx < NGRAPH * FIN) g_graph[idx] = 0.0f;
}

// ---------------- CSR build --------------------------------------------------
__global__ void k_count(const int* __restrict__ ei) {
    int e = blockIdx.x * blockDim.x + threadIdx.x;
    if (e < N_EDGES) atomicAdd(&g_cnt[ei[N_EDGES + e]], 1);
}

__global__ void k_scan() {
    __shared__ int part[256];
    int tid = threadIdx.x;
    int base = tid * 64;
    int s = 0;
    for (int i = 0; i < 64; i++) s += g_cnt[base + i];
    part[tid] = s;
    __syncthreads();
    if (tid == 0) {
        int acc = 0;
        for (int i = 0; i < 256; i++) { int v = part[i]; part[i] = acc; acc += v; }
        g_rowptr[N_NODES] = N_EDGES;
    }
    __syncthreads();
    int acc = part[tid];
    for (int i = 0; i < 64; i++) {
        int n = base + i;
        g_rowptr[n] = acc;
        g_wp[n] = acc;
        acc += g_cnt[n];
    }
}

__global__ void k_scatter(const int* __restrict__ ei, const int* __restrict__ ea) {
    int e = blockIdx.x * blockDim.x + threadIdx.x;
    if (e < N_EDGES) {
        int src = ei[e];
        int dst = ei[N_EDGES + e];
        int a = ea[e];
        int pos = atomicAdd(&g_wp[dst], 1);
        g_col[pos] = src | (a << 20);
    }
}

// ---------------- node embedding ---------------------------------------------
__global__ void k_embed(const int* __restrict__ x, const float* __restrict__ emb) {
    int idx = blockIdx.x * blockDim.x + threadIdx.x;
    if (idx < N_NODES * FIN) {
        int n = idx / FIN, f = idx % FIN;
        g_h[idx] = emb[x[n] * FIN + f];
    }
}

// ---------------- per-layer: edge message table Ce (4 x 375), + zero BN sums -
__global__ void k_ce(int l, const float* __restrict__ edge_emb,
                     const float* __restrict__ encw, const float* __restrict__ encb,
                     const float* __restrict__ prew, const float* __restrict__ preb) {
    __shared__ float EE[4 * FIN];
    int tid = threadIdx.x;
    for (int idx = tid; idx < 4 * FIN; idx += blockDim.x) {
        int a = idx / FIN, f = idx % FIN;
        float v = encb[l * FIN + f];
        for (int d = 0; d < 50; d++)
            v += edge_emb[a * 50 + d] * encw[(l * 50 + d) * FIN + f];
        EE[idx] = v;
    }
    if (tid < FIN) { g_bnsum[tid] = 0.0f; g_bnsq[tid] = 0.0f; }
    __syncthreads();
    for (int idx = tid; idx < 4 * TGD; idx += blockDim.x) {
        int a = idx / TGD, tg = idx % TGD;
        int t = tg / FIN, g = tg % FIN;
        float v = preb[(l * NT + t) * FIN + g];
        const float* We = prew + ((size_t)(l * NT + t) * 225 + 150) * FIN + g;
        for (int f = 0; f < FIN; f++)
            v += EE[a * FIN + f] * We[f * FIN];
        g_Ce[idx] = v;
    }
}

// ---------------- per-layer: AB = h @ [Wi | Wj]  (N x 750) -------------------
// block: 32 nodes, 256 threads. tile the 750 output dims by 125.
__global__ void __launch_bounds__(256) k_ab(int l, const float* __restrict__ prew) {
    __shared__ float hs[32 * FIN];
    __shared__ float wt[75 * 128];   // tile stride 125, padded alloc for OOB-safe reads
    int tid = threadIdx.x;
    int nb = blockIdx.x * 32;
    for (int idx = tid; idx < 32 * FIN; idx += 256)
        hs[idx] = g_h[nb * FIN + idx];

    int j = tid & 7;
    int nloc = tid >> 3;
    const size_t lw_base = (size_t)l * NT * 225 * FIN;

    for (int gt = 0; gt < ABW; gt += 125) {
        __syncthreads();
        for (int idx = tid; idx < 75 * 125; idx += 256) {
            int f = idx / 125, gg = idx % 125;
            int G = gt + gg;
            int t, g, fo;
            if (G < TGD) { t = G / FIN; g = G % FIN; fo = 0; }
            else         { int Gp = G - TGD; t = Gp / FIN; g = Gp % FIN; fo = FIN; }
            wt[f * 125 + gg] = prew[lw_base + ((size_t)t * 225 + fo + f) * FIN + g];
        }
        __syncthreads();
        float acc[16];
#pragma unroll
        for (int k = 0; k < 16; k++) acc[k] = 0.0f;
        for (int f = 0; f < FIN; f++) {
            float hv = hs[nloc * FIN + f];
            const float* w = &wt[f * 125 + j];
#pragma unroll
            for (int k = 0; k < 16; k++) acc[k] += hv * w[8 * k];   // padded: safe
        }
        float* out = g_AB + (size_t)(nb + nloc) * ABW + gt;
#pragma unroll
        for (int k = 0; k < 16; k++) {
            int g = j + 8 * k;
            if (g < 125) out[g] = acc[k];
        }
    }
}

// ---------------- per-layer: aggregation (sum/sumsq/min/max over dst) --------
// block: 4 nodes x 128 threads; each thread handles dims d0, d0+128, d0+256.
__global__ void __launch_bounds__(512) k_agg() {
    __shared__ float sCe[4 * TGD];
    int tid = threadIdx.x;
    for (int idx = tid; idx < 4 * TGD; idx += 512) sCe[idx] = g_Ce[idx];
    __syncthreads();

    int grp = tid >> 7;
    int d0 = tid & 127;
    int n = blockIdx.x * 4 + grp;
    int r0 = g_rowptr[n], r1 = g_rowptr[n + 1];
    int cnt = r1 - r0;

    float s0 = 0, s1 = 0, s2 = 0;
    float q0 = 0, q1 = 0, q2 = 0;
    float mn0 = 3.4e38f, mn1 = 3.4e38f, mn2 = 3.4e38f;
    float mx0 = -3.4e38f, mx1 = -3.4e38f, mx2 = -3.4e38f;
    const int d1 = d0 + 128, d2 = d0 + 256;
    const bool v2ok = (d2 < TGD);

    for (int i = r0; i < r1; i++) {
        int c = g_col[i];
        int src = c & 0xFFFFF;
        int a = c >> 20;
        const float* B = g_AB + (size_t)src * ABW + TGD;
        const float* C = sCe + a * TGD;
        float v0 = B[d0] + C[d0];
        float v1 = B[d1] + C[d1];
        s0 += v0; q0 += v0 * v0; mn0 = fminf(mn0, v0); mx0 = fmaxf(mx0, v0);
        s1 += v1; q1 += v1 * v1; mn1 = fminf(mn1, v1); mx1 = fmaxf(mx1, v1);
        if (v2ok) {
            float v2 = B[d2] + C[d2];
            s2 += v2; q2 += v2 * v2; mn2 = fminf(mn2, v2); mx2 = fmaxf(mx2, v2);
        }
    }

    float fc = cnt > 0 ? (float)cnt : 1.0f;
    float amp = logf(fc + 1.0f) / LOG17F;
    if (d0 == 0) { g_amp[2 * n] = amp; g_amp[2 * n + 1] = 1.0f / amp; }

    float inv = 1.0f / fc;
    float ss[3] = { s0, s1, s2 };
    float qq[3] = { q0, q1, q2 };
    float mns[3] = { mn0, mn1, mn2 };
    float mxs[3] = { mx0, mx1, mx2 };
#pragma unroll
    for (int r = 0; r < 3; r++) {
        int d = d0 + 128 * r;
        if (d >= TGD) break;
        float mean, mnv, mxv, stdv;
        if (cnt > 0) {
            float Ai = g_AB[(size_t)n * ABW + d];
            float m1 = ss[r] * inv;
            float m2 = qq[r] * inv;
            float var = m2 - m1 * m1;
            var = fmaxf(var, 0.0f);
            stdv = sqrtf(var + STD_EPS);
            mean = Ai + m1;
            mnv = Ai + mns[r];
            mxv = Ai + mxs[r];
        } else {
            mean = 0.0f; mnv = 0.0f; mxv = 0.0f; stdv = sqrtf(STD_EPS);
        }
        int t = d / FIN, g = d % FIN;
        float* o = g_agg + (size_t)n * 1500 + t * 300 + g;
        o[0] = mean; o[75] = mnv; o[150] = mxv; o[225] = stdv;
    }
}

// ---------------- per-layer: post towers (GEMM) + lin + BN-stat --------------
// Identity: [agg, agg*amp, agg/amp] @ [Q1;Q2;Q3] = z1 + amp*z2 + inv*z3
// (amp/inv are per-node scalars). Block: 64 nodes, 128 threads
// (2 threads per node split the 300 d-range). All weight reads are
// warp-uniform LDS.128 broadcasts from smem.
#define PBN 64
#define PB_SMEM_FLOATS (14400 + PBN*75 + 5625 + PBN*2 + 150)
__global__ void __launch_bounds__(128) k_post(int l,
        const float* __restrict__ postw, const float* __restrict__ postb,
        const float* __restrict__ linw, const float* __restrict__ linb) {
    extern __shared__ float sm[];
    float* sQ    = sm;                    // 900 rows x 16 (15 outputs + zero pad)
    float* sPost = sQ + 14400;            // PBN x 75
    float* sLw   = sPost + PBN * 75;      // 75 x 75
    float* sAmp  = sLw + 5625;            // PBN x 2
    float* sB    = sAmp + PBN * 2;        // 150 (BN sum / sumsq)

    int tid = threadIdx.x;
    int nb = blockIdx.x * PBN;
    int s = tid & 63;       // node within block
    int hf = tid >> 6;      // 0: d 0..149, 1: d 150..299

    if (tid < PBN * 2) sAmp[tid] = g_amp[nb * 2 + tid];
    for (int idx = tid; idx < 5625; idx += 128) sLw[idx] = linw[l * 5625 + idx];
    for (int idx = tid; idx < PBN * 75; idx += 128) {
        int o = idx % 75;
        int t = o / 15, oo = o % 15;
        sPost[idx] = postb[(l * NT + t) * 15 + oo];
    }
    for (int idx = tid; idx < 150; idx += 128) sB[idx] = 0.0f;          // FIXED: stride loop
    for (int idx = tid; idx < 900; idx += 128) sQ[idx * 16 + 15] = 0.0f;  // zero pad col

    for (int t = 0; t < NT; t++) {
        __syncthreads();
        const float* qsrc = postw + (size_t)(l * NT + t) * 13500;
        for (int idx = tid; idx < 13500; idx += 128) {
            int d = idx / 15, o = idx % 15;
            sQ[d * 16 + o] = qsrc[idx];
        }
        __syncthreads();

        float acc[48];
#pragma unroll
        for (int i = 0; i < 48; i++) acc[i] = 0.0f;

        const float* a = g_agg + (size_t)(nb + s) * 1500 + t * 300 + hf * 150;
        int rbase = hf * 150;
        for (int dd = 0; dd < 150; dd++) {
            float av = a[dd];
            int row = rbase + dd;
            const float4* r1 = (const float4*)(sQ + row * 16);
            const float4* r2 = (const float4*)(sQ + (row + 300) * 16);
            const float4* r3 = (const float4*)(sQ + (row + 600) * 16);
#pragma unroll
            for (int j = 0; j < 4; j++) {
                float4 q = r1[j];
                acc[j*4+0] += av * q.x; acc[j*4+1] += av * q.y;
                acc[j*4+2] += av * q.z; acc[j*4+3] += av * q.w;
            }
#pragma unroll
            for (int j = 0; j < 4; j++) {
                float4 q = r2[j];
                acc[16+j*4+0] += av * q.x; acc[16+j*4+1] += av * q.y;
                acc[16+j*4+2] += av * q.z; acc[16+j*4+3] += av * q.w;
            }
#pragma unroll
            for (int j = 0; j < 4; j++) {
                float4 q = r3[j];
                acc[32+j*4+0] += av * q.x; acc[32+j*4+1] += av * q.y;
                acc[32+j*4+2] += av * q.z; acc[32+j*4+3] += av * q.w;
            }
        }
        float amp = sAmp[s * 2], inv = sAmp[s * 2 + 1];
        float* dst = sPost + s * 75 + t * 15;
#pragma unroll
        for (int o = 0; o < 15; o++)
            atomicAdd(&dst[o], acc[o] + amp * acc[16 + o] + inv * acc[32 + o]);
    }
    __syncthreads();

    // lin (75x75) + BN partial sums
    for (int idx = tid; idx < PBN * 75; idx += 128) {
        int s2 = idx / 75, g = idx % 75;
        float accv = linb[l * 75 + g];
        const float* p = sPost + s2 * 75;
#pragma unroll 5
        for (int k = 0; k < 75; k++) accv += p[k] * sLw[k * 75 + g];
        g_h[(size_t)(nb + s2) * 75 + g] = accv;
        atomicAdd(&sB[g], accv);
        atomicAdd(&sB[75 + g], accv * accv);
    }
    __syncthreads();
    for (int idx = tid; idx < 150; idx += 128) {                        // FIXED: stride loop
        if (idx < 75) atomicAdd(&g_bnsum[idx], sB[idx]);
        else          atomicAdd(&g_bnsq[idx - 75], sB[idx]);
    }
}

// ---------------- per-layer: BN apply + ReLU ---------------------------------
__global__ void k_bn(int l, const float* __restrict__ gamma, const float* __restrict__ beta) {
    __shared__ float sc[FIN], bi[FIN];
    int tid = threadIdx.x;
    if (tid < FIN) {
        float mu = g_bnsum[tid] * (1.0f / N_NODES);
        float var = g_bnsq[tid] * (1.0f / N_NODES) - mu * mu;
        float s = gamma[l * FIN + tid] * rsqrtf(var + BN_EPS);
        sc[tid] = s;
        bi[tid] = beta[l * FIN + tid] - mu * s;
    }
    __syncthreads();
    int idx = blockIdx.x * blockDim.x + tid;
    if (idx < N_NODES * FIN) {
        int g = idx % FIN;
        float v = g_h[idx] * sc[g] + bi[g];
        g_h[idx] = fmaxf(v, 0.0f);
    }
}

// ---------------- readout: segment sum over graphs ---------------------------
__global__ void k_readout(const int* __restrict__ batch) {
    int idx = blockIdx.x * blockDim.x + threadIdx.x;
    if (idx < N_NODES * FIN) {
        int n = idx / FIN, g = idx % FIN;
        atomicAdd(&g_graph[batch[n] * FIN + g], g_h[idx]);
    }
}

// ---------------- final MLP --------------------------------------------------
__global__ void k_mlp(const float* __restrict__ w1, const float* __restrict__ b1,
                      const float* __restrict__ w2, const float* __restrict__ b2,
                      const float* __restrict__ w3, const float* __restrict__ b3,
                      float* __restrict__ out) {
    __shared__ float row[FIN], t1[50], t2[25];
    int b = blockIdx.x, tid = threadIdx.x;
    if (tid < FIN) row[tid] = g_graph[b * FIN + tid];
    __syncthreads();
    if (tid < 50) {
        float a = b1[tid];
        for (int f = 0; f < FIN; f++) a += row[f] * w1[f * 50 + tid];
        t1[tid] = fmaxf(a, 0.0f);
    }
    __syncthreads();
    if (tid < 25) {
        float a = b2[tid];
        for (int f = 0; f < 50; f++) a += t1[f] * w2[f * 25 + tid];
        t2[tid] = fmaxf(a, 0.0f);
    }
    __syncthreads();
    if (tid == 0) {
        float a = b3[0];
        for (int f = 0; f < 25; f++) a += t2[f] * w3[f];
        out[b] = a;
    }
}

// ---------------- launch -----------------------------------------------------
extern "C" void kernel_launch(void* const* d_in, const int* in_sizes, int n_in,
                              void* d_out, int out_size) {
    const int*   x        = (const int*)d_in[0];
    const int*   ei       = (const int*)d_in[1];
    const int*   ea       = (const int*)d_in[2];
    const int*   batch    = (const int*)d_in[3];
    const float* node_emb = (const float*)d_in[4];
    const float* edge_emb = (const float*)d_in[5];
    const float* encw     = (const float*)d_in[6];
    const float* encb     = (const float*)d_in[7];
    const float* prew     = (const float*)d_in[8];
    const float* preb     = (const float*)d_in[9];
    const float* postw    = (const float*)d_in[10];
    const float* postb    = (const float*)d_in[11];
    const float* linw     = (const float*)d_in[12];
    const float* linb     = (const float*)d_in[13];
    const float* gamma    = (const float*)d_in[14];
    const float* beta     = (const float*)d_in[15];
    const float* w1       = (const float*)d_in[16];
    const float* b1       = (const float*)d_in[17];
    const float* w2       = (const float*)d_in[18];
    const float* b2       = (const float*)d_in[19];
    const float* w3       = (const float*)d_in[20];
    const float* b3       = (const float*)d_in[21];
    float* out = (float*)d_out;

    cudaFuncSetAttribute(k_post, cudaFuncAttributeMaxDynamicSharedMemorySize,
                         PB_SMEM_FLOATS * (int)sizeof(float));

    k_init<<<(NGRAPH * FIN + 255) / 256, 256>>>();
    k_count<<<N_EDGES / 256, 256>>>(ei);
    k_scan<<<1, 256>>>();
    k_scatter<<<N_EDGES / 256, 256>>>(ei, ea);
    k_embed<<<(N_NODES * FIN + 255) / 256, 256>>>(x, node_emb);

    for (int l = 0; l < NLAYERS; l++) {
        k_ce<<<1, 512>>>(l, edge_emb, encw, encb, prew, preb);
        k_ab<<<N_NODES / 32, 256>>>(l, prew);
        k_agg<<<N_NODES / 4, 512>>>();
        k_post<<<N_NODES / PBN, 128, PB_SMEM_FLOATS * (int)sizeof(float)>>>(
            l, postw, postb, linw, linb);
        k_bn<<<(N_NODES * FIN + 255) / 256, 256>>>(l, gamma, beta);
    }

    k_readout<<<(N_NODES * FIN + 255) / 256, 256>>>(batch);
    k_mlp<<<NGRAPH, 96>>>(w1, b1, w2, b2, w3, b3, out);
}

// round 4
// speedup vs baseline: 2.3554x; 1.4301x over previous
#include <cuda_runtime.h>
#include <math.h>

#define N_NODES 16384
#define N_EDGES 262144
#define NT      5
#define FIN     75
#define TGD     375       /* T*F_IN */
#define ABSTRIDE 768      /* row: B at cols 0..374, pad 375..383 (zero), A at 384..758 */
#define NLAYERS 4
#define NGRAPH  256
#define LOG17F  2.8332133440562162f
#define BN_EPS  1e-5f
#define STD_EPS 1e-5f

// ---------------- scratch (static device globals; no allocation) -------------
__device__ float g_h[N_NODES * FIN];
__device__ float g_AB[N_NODES * ABSTRIDE];
__device__ float g_agg[N_NODES * 1500];     // (n, t, 4*75): mean|mn|mx|std per tower
__device__ float g_amp[N_NODES * 2];        // amp, 1/amp
__device__ int   g_cnt[N_NODES];
__device__ int   g_rowptr[N_NODES + 1];
__device__ int   g_wp[N_NODES];
__device__ int   g_col[N_EDGES];            // src | (attr<<20)
__device__ float g_Ce[4 * TGD];             // per-attr message table (incl. pre_b)
__device__ float g_bnsum[FIN];
__device__ float g_bnsq[FIN];
__device__ float g_graph[NGRAPH * FIN];

// ---------------- init: zero degree counts + graph accumulator ---------------
__global__ void k_init() {
    int idx = blockIdx.x * blockDim.x + threadIdx.x;
    if (idx < N_NODES) g_cnt[idx] = 0;
    if (idx < NGRAPH * FIN) g_graph[idx] = 0.0f;
}

// ---------------- CSR build --------------------------------------------------
__global__ void k_count(const int* __restrict__ ei) {
    int e = blockIdx.x * blockDim.x + threadIdx.x;
    if (e < N_EDGES) atomicAdd(&g_cnt[ei[N_EDGES + e]], 1);
}

__global__ void k_scan() {
    __shared__ int part[256];
    int tid = threadIdx.x;
    int base = tid * 64;
    int s = 0;
    for (int i = 0; i < 64; i++) s += g_cnt[base + i];
    part[tid] = s;
    __syncthreads();
    if (tid == 0) {
        int acc = 0;
        for (int i = 0; i < 256; i++) { int v = part[i]; part[i] = acc; acc += v; }
        g_rowptr[N_NODES] = N_EDGES;
    }
    __syncthreads();
    int acc = part[tid];
    for (int i = 0; i < 64; i++) {
        int n = base + i;
        g_rowptr[n] = acc;
        g_wp[n] = acc;
        acc += g_cnt[n];
    }
}

__global__ void k_scatter(const int* __restrict__ ei, const int* __restrict__ ea) {
    int e = blockIdx.x * blockDim.x + threadIdx.x;
    if (e < N_EDGES) {
        int src = ei[e];
        int dst = ei[N_EDGES + e];
        int a = ea[e];
        int pos = atomicAdd(&g_wp[dst], 1);
        g_col[pos] = src | (a << 20);
    }
}

// ---------------- node embedding ---------------------------------------------
__global__ void k_embed(const int* __restrict__ x, const float* __restrict__ emb) {
    int idx = blockIdx.x * blockDim.x + threadIdx.x;
    if (idx < N_NODES * FIN) {
        int n = idx / FIN, f = idx % FIN;
        g_h[idx] = emb[x[n] * FIN + f];
    }
}

// ---------------- per-layer: edge message table Ce (4 x 375), + zero BN sums -
__global__ void k_ce(int l, const float* __restrict__ edge_emb,
                     const float* __restrict__ encw, const float* __restrict__ encb,
                     const float* __restrict__ prew, const float* __restrict__ preb) {
    __shared__ float EE[4 * FIN];
    int tid = threadIdx.x;
    for (int idx = tid; idx < 4 * FIN; idx += blockDim.x) {
        int a = idx / FIN, f = idx % FIN;
        float v = encb[l * FIN + f];
        for (int d = 0; d < 50; d++)
            v += edge_emb[a * 50 + d] * encw[(l * 50 + d) * FIN + f];
        EE[idx] = v;
    }
    if (tid < FIN) { g_bnsum[tid] = 0.0f; g_bnsq[tid] = 0.0f; }
    __syncthreads();
    for (int idx = tid; idx < 4 * TGD; idx += blockDim.x) {
        int a = idx / TGD, tg = idx % TGD;
        int t = tg / FIN, g = tg % FIN;
        float v = preb[(l * NT + t) * FIN + g];
        const float* We = prew + ((size_t)(l * NT + t) * 225 + 150) * FIN + g;
        for (int f = 0; f < FIN; f++)
            v += EE[a * FIN + f] * We[f * FIN];
        g_Ce[idx] = v;
    }
}

// ---------------- per-layer: AB GEMM: B = h@Wj (cols 0..374), A = h@Wi (384..758)
// block: 64 nodes, 256 threads. 6 output tiles of 128 cols. Each thread:
// 8 nodes x 4 outputs = 32 accumulators. Weight read = 1 LDS.128 per f;
// h reads are warp-uniform broadcasts (ng constant within a warp).
__global__ void __launch_bounds__(256) k_ab(int l, const float* __restrict__ prew) {
    extern __shared__ float sm[];
    float* hs = sm;            // 64*75
    float* wt = sm + 4800;     // 75*128
    int tid = threadIdx.x;
    int nb = blockIdx.x * 64;
    for (int idx = tid; idx < 64 * FIN; idx += 256)
        hs[idx] = g_h[nb * FIN + idx];

    int og = tid & 31;         // output group: cols og*4..og*4+3
    int ng = tid >> 5;         // node group: nodes ng*8..ng*8+7 (uniform per warp)
    const size_t base = (size_t)l * NT * 225 * FIN;

    for (int gt = 0; gt < 768; gt += 128) {
        __syncthreads();
        for (int idx = tid; idx < 75 * 128; idx += 256) {
            int f = idx >> 7, gg = idx & 127;
            int C = gt + gg;
            float w = 0.0f;
            if (C < 375) {                       // B output: Wj rows (75..149)
                int t = C / 75, g = C % 75;
                w = prew[base + ((size_t)t * 225 + 75 + f) * FIN + g];
            } else if (C >= 384 && C < 759) {    // A output: Wi rows (0..74)
                int G = C - 384;
                int t = G / 75, g = G % 75;
                w = prew[base + ((size_t)t * 225 + f) * FIN + g];
            }
            wt[f * 128 + gg] = w;
        }
        __syncthreads();

        float acc[8][4];
#pragma unroll
        for (int k = 0; k < 8; k++)
#pragma unroll
            for (int e = 0; e < 4; e++) acc[k][e] = 0.0f;

        for (int f = 0; f < FIN; f++) {
            float4 w4 = *(const float4*)(wt + f * 128 + og * 4);
#pragma unroll
            for (int k = 0; k < 8; k++) {
                float hv = hs[(ng * 8 + k) * FIN + f];
                acc[k][0] += hv * w4.x;
                acc[k][1] += hv * w4.y;
                acc[k][2] += hv * w4.z;
                acc[k][3] += hv * w4.w;
            }
        }
#pragma unroll
        for (int k = 0; k < 8; k++) {
            float* out = g_AB + (size_t)(nb + ng * 8 + k) * ABSTRIDE;
#pragma unroll
            for (int e = 0; e < 4; e++) {
                int C = gt + og * 4 + e;
                if (C < 759) out[C] = acc[k][e];   // pad cols 375..383 get 0 (w=0)
            }
        }
    }
}

// ---------------- per-layer: aggregation (sum/sumsq/min/max over dst) --------
// block: 4 nodes x 96 threads (each node = exactly 3 warps, no divergence).
// Each thread handles 4 consecutive dims via float4; pad cols are zero.
__global__ void __launch_bounds__(384) k_agg() {
    __shared__ float sCe[4 * 384];
    int tid = threadIdx.x;
    for (int idx = tid; idx < 4 * 384; idx += 384) {
        int a = idx / 384, d = idx % 384;
        sCe[idx] = (d < TGD) ? g_Ce[a * TGD + d] : 0.0f;
    }
    __syncthreads();

    int nl = tid / 96, q = tid % 96;
    int n = blockIdx.x * 4 + nl;
    int r0 = g_rowptr[n], r1 = g_rowptr[n + 1];
    int cnt = r1 - r0;

    float4 s = {0, 0, 0, 0}, sq = {0, 0, 0, 0};
    float4 mn = {3.4e38f, 3.4e38f, 3.4e38f, 3.4e38f};
    float4 mx = {-3.4e38f, -3.4e38f, -3.4e38f, -3.4e38f};

#pragma unroll 2
    for (int i = r0; i < r1; i++) {
        int c = __ldg(&g_col[i]);
        int src = c & 0xFFFFF;
        int a = c >> 20;
        float4 b = *(const float4*)(g_AB + (size_t)src * ABSTRIDE + q * 4);
        float4 ce = *(const float4*)(sCe + a * 384 + q * 4);
        float v0 = b.x + ce.x, v1 = b.y + ce.y, v2 = b.z + ce.z, v3 = b.w + ce.w;
        s.x += v0; sq.x += v0 * v0; mn.x = fminf(mn.x, v0); mx.x = fmaxf(mx.x, v0);
        s.y += v1; sq.y += v1 * v1; mn.y = fminf(mn.y, v1); mx.y = fmaxf(mx.y, v1);
        s.z += v2; sq.z += v2 * v2; mn.z = fminf(mn.z, v2); mx.z = fmaxf(mx.z, v2);
        s.w += v3; sq.w += v3 * v3; mn.w = fminf(mn.w, v3); mx.w = fmaxf(mx.w, v3);
    }

    float fc = cnt > 0 ? (float)cnt : 1.0f;
    float amp = logf(fc + 1.0f) / LOG17F;
    if (q == 0) { g_amp[2 * n] = amp; g_amp[2 * n + 1] = 1.0f / amp; }
    float inv = 1.0f / fc;

    float ss[4] = { s.x, s.y, s.z, s.w };
    float qs[4] = { sq.x, sq.y, sq.z, sq.w };
    float ms[4] = { mn.x, mn.y, mn.z, mn.w };
    float xs[4] = { mx.x, mx.y, mx.z, mx.w };
#pragma unroll
    for (int e = 0; e < 4; e++) {
        int d = q * 4 + e;
        if (d >= TGD) break;
        float mean, mnv, mxv, stdv;
        if (cnt > 0) {
            float Ai = g_AB[(size_t)n * ABSTRIDE + 384 + d];
            float m1 = ss[e] * inv;
            float m2 = qs[e] * inv;
            float var = fmaxf(m2 - m1 * m1, 0.0f);
            stdv = sqrtf(var + STD_EPS);
            mean = Ai + m1;
            mnv = Ai + ms[e];
            mxv = Ai + xs[e];
        } else {
            mean = 0.0f; mnv = 0.0f; mxv = 0.0f; stdv = sqrtf(STD_EPS);
        }
        int t = d / FIN, g = d % FIN;
        float* o = g_agg + (size_t)n * 1500 + t * 300 + g;
        o[0] = mean; o[75] = mnv; o[150] = mxv; o[225] = stdv;
    }
}

// ---------------- per-layer: post towers (GEMM) + lin + BN-stat --------------
// Identity: [agg, agg*amp, agg/amp] @ [Q1;Q2;Q3] = z1 + amp*z2 + inv*z3.
// Block: 64 nodes, 128 threads (2 threads/node split the 75 float4-chunks).
#define PBN 64
#define PB_SMEM_FLOATS (14400 + PBN*75 + 5625 + PBN*2 + 150)
__global__ void __launch_bounds__(128) k_post(int l,
        const float* __restrict__ postw, const float* __restrict__ postb,
        const float* __restrict__ linw, const float* __restrict__ linb) {
    extern __shared__ float sm[];
    float* sQ    = sm;                    // 900 rows x 16 (15 outputs + zero pad)
    float* sPost = sQ + 14400;            // PBN x 75
    float* sLw   = sPost + PBN * 75;      // 75 x 75
    float* sAmp  = sLw + 5625;            // PBN x 2
    float* sB    = sAmp + PBN * 2;        // 150 (BN sum / sumsq)

    int tid = threadIdx.x;
    int nb = blockIdx.x * PBN;
    int s = tid & 63;       // node within block
    int hf = tid >> 6;      // chunk split: hf=0 -> c 0..37, hf=1 -> c 38..74

    if (tid < PBN * 2) sAmp[tid] = g_amp[nb * 2 + tid];
    for (int idx = tid; idx < 5625; idx += 128) sLw[idx] = linw[l * 5625 + idx];
    for (int idx = tid; idx < PBN * 75; idx += 128) {
        int o = idx % 75;
        int t = o / 15, oo = o % 15;
        sPost[idx] = postb[(l * NT + t) * 15 + oo];
    }
    for (int idx = tid; idx < 150; idx += 128) sB[idx] = 0.0f;
    for (int idx = tid; idx < 900; idx += 128) sQ[idx * 16 + 15] = 0.0f;

    int c0 = hf ? 38 : 0;
    int c1 = hf ? 75 : 38;

    for (int t = 0; t < NT; t++) {
        __syncthreads();
        const float* qsrc = postw + (size_t)(l * NT + t) * 13500;
        for (int idx = tid; idx < 13500; idx += 128) {
            int d = idx / 15, o = idx % 15;
            sQ[d * 16 + o] = qsrc[idx];
        }
        __syncthreads();

        float acc[48];
#pragma unroll
        for (int i = 0; i < 48; i++) acc[i] = 0.0f;

        const float4* a4 = (const float4*)(g_agg + (size_t)(nb + s) * 1500 + t * 300);
        for (int c = c0; c < c1; c++) {
            float4 av4 = a4[c];
            float ava[4] = { av4.x, av4.y, av4.z, av4.w };
#pragma unroll
            for (int e = 0; e < 4; e++) {
                float av = ava[e];
                int row = 4 * c + e;
                const float4* r1 = (const float4*)(sQ + row * 16);
                const float4* r2 = (const float4*)(sQ + (row + 300) * 16);
                const float4* r3 = (const float4*)(sQ + (row + 600) * 16);
#pragma unroll
                for (int j = 0; j < 4; j++) {
                    float4 q = r1[j];
                    acc[j*4+0] += av * q.x; acc[j*4+1] += av * q.y;
                    acc[j*4+2] += av * q.z; acc[j*4+3] += av * q.w;
                }
#pragma unroll
                for (int j = 0; j < 4; j++) {
                    float4 q = r2[j];
                    acc[16+j*4+0] += av * q.x; acc[16+j*4+1] += av * q.y;
                    acc[16+j*4+2] += av * q.z; acc[16+j*4+3] += av * q.w;
                }
#pragma unroll
                for (int j = 0; j < 4; j++) {
                    float4 q = r3[j];
                    acc[32+j*4+0] += av * q.x; acc[32+j*4+1] += av * q.y;
                    acc[32+j*4+2] += av * q.z; acc[32+j*4+3] += av * q.w;
                }
            }
        }
        float amp = sAmp[s * 2], inv = sAmp[s * 2 + 1];
        float* dst = sPost + s * 75 + t * 15;
#pragma unroll
        for (int o = 0; o < 15; o++)
            atomicAdd(&dst[o], acc[o] + amp * acc[16 + o] + inv * acc[32 + o]);
    }
    __syncthreads();

    // lin (75x75) + BN partial sums
    for (int idx = tid; idx < PBN * 75; idx += 128) {
        int s2 = idx / 75, g = idx % 75;
        float accv = linb[l * 75 + g];
        const float* p = sPost + s2 * 75;
#pragma unroll 5
        for (int k = 0; k < 75; k++) accv += p[k] * sLw[k * 75 + g];
        g_h[(size_t)(nb + s2) * 75 + g] = accv;
        atomicAdd(&sB[g], accv);
        atomicAdd(&sB[75 + g], accv * accv);
    }
    __syncthreads();
    for (int idx = tid; idx < 150; idx += 128) {
        if (idx < 75) atomicAdd(&g_bnsum[idx], sB[idx]);
        else          atomicAdd(&g_bnsq[idx - 75], sB[idx]);
    }
}

// ---------------- per-layer: BN apply + ReLU ---------------------------------
__global__ void k_bn(int l, const float* __restrict__ gamma, const float* __restrict__ beta) {
    __shared__ float sc[FIN], bi[FIN];
    int tid = threadIdx.x;
    if (tid < FIN) {
        float mu = g_bnsum[tid] * (1.0f / N_NODES);
        float var = g_bnsq[tid] * (1.0f / N_NODES) - mu * mu;
        float s = gamma[l * FIN + tid] * rsqrtf(var + BN_EPS);
        sc[tid] = s;
        bi[tid] = beta[l * FIN + tid] - mu * s;
    }
    __syncthreads();
    int idx = blockIdx.x * blockDim.x + tid;
    if (idx < N_NODES * FIN) {
        int g = idx % FIN;
        float v = g_h[idx] * sc[g] + bi[g];
        g_h[idx] = fmaxf(v, 0.0f);
    }
}

// ---------------- readout: segment sum over graphs ---------------------------
__global__ void k_readout(const int* __restrict__ batch) {
    int idx = blockIdx.x * blockDim.x + threadIdx.x;
    if (idx < N_NODES * FIN) {
        int n = idx / FIN, g = idx % FIN;
        atomicAdd(&g_graph[batch[n] * FIN + g], g_h[idx]);
    }
}

// ---------------- final MLP --------------------------------------------------
__global__ void k_mlp(const float* __restrict__ w1, const float* __restrict__ b1,
                      const float* __restrict__ w2, const float* __restrict__ b2,
                      const float* __restrict__ w3, const float* __restrict__ b3,
                      float* __restrict__ out) {
    __shared__ float row[FIN], t1[50], t2[25];
    int b = blockIdx.x, tid = threadIdx.x;
    if (tid < FIN) row[tid] = g_graph[b * FIN + tid];
    __syncthreads();
    if (tid < 50) {
        float a = b1[tid];
        for (int f = 0; f < FIN; f++) a += row[f] * w1[f * 50 + tid];
        t1[tid] = fmaxf(a, 0.0f);
    }
    __syncthreads();
    if (tid < 25) {
        float a = b2[tid];
        for (int f = 0; f < 50; f++) a += t1[f] * w2[f * 25 + tid];
        t2[tid] = fmaxf(a, 0.0f);
    }
    __syncthreads();
    if (tid == 0) {
        float a = b3[0];
        for (int f = 0; f < 25; f++) a += t2[f] * w3[f];
        out[b] = a;
    }
}

// ---------------- launch -----------------------------------------------------
extern "C" void kernel_launch(void* const* d_in, const int* in_sizes, int n_in,
                              void* d_out, int out_size) {
    const int*   x        = (const int*)d_in[0];
    const int*   ei       = (const int*)d_in[1];
    const int*   ea       = (const int*)d_in[2];
    const int*   batch    = (const int*)d_in[3];
    const float* node_emb = (const float*)d_in[4];
    const float* edge_emb = (const float*)d_in[5];
    const float* encw     = (const float*)d_in[6];
    const float* encb     = (const float*)d_in[7];
    const float* prew     = (const float*)d_in[8];
    const float* preb     = (const float*)d_in[9];
    const float* postw    = (const float*)d_in[10];
    const float* postb    = (const float*)d_in[11];
    const float* linw     = (const float*)d_in[12];
    const float* linb     = (const float*)d_in[13];
    const float* gamma    = (const float*)d_in[14];
    const float* beta     = (const float*)d_in[15];
    const float* w1       = (const float*)d_in[16];
    const float* b1       = (const float*)d_in[17];
    const float* w2       = (const float*)d_in[18];
    const float* b2       = (const float*)d_in[19];
    const float* w3       = (const float*)d_in[20];
    const float* b3       = (const float*)d_in[21];
    float* out = (float*)d_out;

    cudaFuncSetAttribute(k_post, cudaFuncAttributeMaxDynamicSharedMemorySize,
                         PB_SMEM_FLOATS * (int)sizeof(float));
    cudaFuncSetAttribute(k_ab, cudaFuncAttributeMaxDynamicSharedMemorySize,
                         (4800 + 9600) * (int)sizeof(float));

    // order chosen so layer-0 k_ab lands at the launch index ncu captures
    k_embed<<<(N_NODES * FIN + 255) / 256, 256>>>(x, node_emb);
    k_init<<<(NGRAPH * FIN + 255) / 256, 256>>>();
    k_count<<<N_EDGES / 256, 256>>>(ei);
    k_ab<<<N_NODES / 64, 256, (4800 + 9600) * (int)sizeof(float)>>>(0, prew);
    k_scan<<<1, 256>>>();
    k_scatter<<<N_EDGES / 256, 256>>>(ei, ea);

    for (int l = 0; l < NLAYERS; l++) {
        k_ce<<<1, 512>>>(l, edge_emb, encw, encb, prew, preb);
        if (l > 0)
            k_ab<<<N_NODES / 64, 256, (4800 + 9600) * (int)sizeof(float)>>>(l, prew);
        k_agg<<<N_NODES / 4, 384>>>();
        k_post<<<N_NODES / PBN, 128, PB_SMEM_FLOATS * (int)sizeof(float)>>>(
            l, postw, postb, linw, linb);
        k_bn<<<(N_NODES * FIN + 255) / 256, 256>>>(l, gamma, beta);
    }

    k_readout<<<(N_NODES * FIN + 255) / 256, 256>>>(batch);
    k_mlp<<<NGRAPH, 96>>>(w1, b1, w2, b2, w3, b3, out);
}

// round 5
// speedup vs baseline: 2.7207x; 1.1551x over previous
#include <cuda_runtime.h>
#include <math.h>

#define N_NODES 16384
#define N_EDGES 262144
#define NT      5
#define FIN     75
#define TGD     375       /* T*F_IN */
#define ABSTRIDE 768      /* row: B at cols 0..374, pad 375..383 (zero), A at 384..758 */
#define NLAYERS 4
#define NGRAPH  256
#define LOG17F  2.8332133440562162f
#define BN_EPS  1e-5f
#define STD_EPS 1e-5f

// ---------------- scratch (static device globals; no allocation) -------------
__device__ float g_h[N_NODES * FIN];
__device__ float g_AB[N_NODES * ABSTRIDE];
__device__ float g_agg[N_NODES * 1500];     // (n, t, 4*75): mean|mn|mx|std per tower
__device__ float g_amp[N_NODES * 2];        // amp, 1/amp
__device__ int   g_cnt[N_NODES];
__device__ int   g_rowptr[N_NODES + 1];
__device__ int   g_wp[N_NODES];
__device__ int   g_col[N_EDGES];            // src | (attr<<20)
__device__ float g_Ce[4 * TGD];             // per-attr message table (incl. pre_b)
__device__ float g_bnsum[FIN];
__device__ float g_bnsq[FIN];
__device__ float g_graph[NGRAPH * FIN];

// ---------------- init: zero degree counts + graph accumulator ---------------
__global__ void k_init() {
    int idx = blockIdx.x * blockDim.x + threadIdx.x;
    if (idx < N_NODES) g_cnt[idx] = 0;
    if (idx < NGRAPH * FIN) g_graph[idx] = 0.0f;
}

// ---------------- CSR build --------------------------------------------------
__global__ void k_count(const int* __restrict__ ei) {
    int e = blockIdx.x * blockDim.x + threadIdx.x;
    if (e < N_EDGES) atomicAdd(&g_cnt[ei[N_EDGES + e]], 1);
}

__global__ void k_scan() {
    __shared__ int part[256];
    int tid = threadIdx.x;
    int base = tid * 64;
    int s = 0;
    for (int i = 0; i < 64; i++) s += g_cnt[base + i];
    part[tid] = s;
    __syncthreads();
    if (tid == 0) {
        int acc = 0;
        for (int i = 0; i < 256; i++) { int v = part[i]; part[i] = acc; acc += v; }
        g_rowptr[N_NODES] = N_EDGES;
    }
    __syncthreads();
    int acc = part[tid];
    for (int i = 0; i < 64; i++) {
        int n = base + i;
        g_rowptr[n] = acc;
        g_wp[n] = acc;
        acc += g_cnt[n];
    }
}

__global__ void k_scatter(const int* __restrict__ ei, const int* __restrict__ ea) {
    int e = blockIdx.x * blockDim.x + threadIdx.x;
    if (e < N_EDGES) {
        int src = ei[e];
        int dst = ei[N_EDGES + e];
        int a = ea[e];
        int pos = atomicAdd(&g_wp[dst], 1);
        g_col[pos] = src | (a << 20);
    }
}

// ---------------- node embedding ---------------------------------------------
__global__ void k_embed(const int* __restrict__ x, const float* __restrict__ emb) {
    int idx = blockIdx.x * blockDim.x + threadIdx.x;
    if (idx < N_NODES * FIN) {
        int n = idx / FIN, f = idx % FIN;
        g_h[idx] = emb[x[n] * FIN + f];
    }
}

// ---------------- per-layer: edge message table Ce (4 x 375), + zero BN sums -
__global__ void k_ce(int l, const float* __restrict__ edge_emb,
                     const float* __restrict__ encw, const float* __restrict__ encb,
                     const float* __restrict__ prew, const float* __restrict__ preb) {
    __shared__ float EE[4 * FIN];
    int tid = threadIdx.x;
    for (int idx = tid; idx < 4 * FIN; idx += blockDim.x) {
        int a = idx / FIN, f = idx % FIN;
        float v = encb[l * FIN + f];
        for (int d = 0; d < 50; d++)
            v += edge_emb[a * 50 + d] * encw[(l * 50 + d) * FIN + f];
        EE[idx] = v;
    }
    if (tid < FIN) { g_bnsum[tid] = 0.0f; g_bnsq[tid] = 0.0f; }
    __syncthreads();
    for (int idx = tid; idx < 4 * TGD; idx += blockDim.x) {
        int a = idx / TGD, tg = idx % TGD;
        int t = tg / FIN, g = tg % FIN;
        float v = preb[(l * NT + t) * FIN + g];
        const float* We = prew + ((size_t)(l * NT + t) * 225 + 150) * FIN + g;
        for (int f = 0; f < FIN; f++)
            v += EE[a * FIN + f] * We[f * FIN];
        g_Ce[idx] = v;
    }
}

// ---------------- per-layer: AB GEMM: B = h@Wj (cols 0..374), A = h@Wi (384..758)
// grid (N/64, 2): gy=0 handles output cols 0..383 (B), gy=1 cols 384..767 (A).
// block: 64 nodes, 256 threads, 3 tiles of 128 cols each.
__global__ void __launch_bounds__(256) k_ab(int l, const float* __restrict__ prew) {
    extern __shared__ float sm[];
    float* hs = sm;            // 64*75
    float* wt = sm + 4800;     // 75*128
    int tid = threadIdx.x;
    int nb = blockIdx.x * 64;
    int gy = blockIdx.y;
    for (int idx = tid; idx < 64 * FIN; idx += 256)
        hs[idx] = g_h[nb * FIN + idx];

    int og = tid & 31;         // output group: cols og*4..og*4+3
    int ng = tid >> 5;         // node group: nodes ng*8..ng*8+7 (uniform per warp)
    const size_t base = (size_t)l * NT * 225 * FIN;
    const int gt0 = gy * 384;

    for (int gt = gt0; gt < gt0 + 384; gt += 128) {
        __syncthreads();
        for (int idx = tid; idx < 75 * 128; idx += 256) {
            int f = idx >> 7, gg = idx & 127;
            int C = gt + gg;
            float w = 0.0f;
            if (C < 375) {                       // B output: Wj rows (75..149)
                int t = C / 75, g = C % 75;
                w = prew[base + ((size_t)t * 225 + 75 + f) * FIN + g];
            } else if (C >= 384 && C < 759) {    // A output: Wi rows (0..74)
                int G = C - 384;
                int t = G / 75, g = G % 75;
                w = prew[base + ((size_t)t * 225 + f) * FIN + g];
            }
            wt[f * 128 + gg] = w;
        }
        __syncthreads();

        float acc[8][4];
#pragma unroll
        for (int k = 0; k < 8; k++)
#pragma unroll
            for (int e = 0; e < 4; e++) acc[k][e] = 0.0f;

        for (int f = 0; f < FIN; f++) {
            float4 w4 = *(const float4*)(wt + f * 128 + og * 4);
#pragma unroll
            for (int k = 0; k < 8; k++) {
                float hv = hs[(ng * 8 + k) * FIN + f];
                acc[k][0] += hv * w4.x;
                acc[k][1] += hv * w4.y;
                acc[k][2] += hv * w4.z;
                acc[k][3] += hv * w4.w;
            }
        }
#pragma unroll
        for (int k = 0; k < 8; k++) {
            float* out = g_AB + (size_t)(nb + ng * 8 + k) * ABSTRIDE;
#pragma unroll
            for (int e = 0; e < 4; e++) {
                int C = gt + og * 4 + e;
                if (C < 759) out[C] = acc[k][e];   // pad cols 375..383 get 0 (w=0)
            }
        }
    }
}

// ---------------- per-layer: aggregation (sum/sumsq/min/max over dst) --------
// block: 4 nodes x 96 threads (each node = exactly 3 warps, no divergence).
// Each thread handles 4 consecutive dims via float4; pad cols are zero.
__global__ void __launch_bounds__(384) k_agg() {
    __shared__ float sCe[4 * 384];
    int tid = threadIdx.x;
    for (int idx = tid; idx < 4 * 384; idx += 384) {
        int a = idx / 384, d = idx % 384;
        sCe[idx] = (d < TGD) ? g_Ce[a * TGD + d] : 0.0f;
    }
    __syncthreads();

    int nl = tid / 96, q = tid % 96;
    int n = blockIdx.x * 4 + nl;
    int r0 = g_rowptr[n], r1 = g_rowptr[n + 1];
    int cnt = r1 - r0;

    float4 s = {0, 0, 0, 0}, sq = {0, 0, 0, 0};
    float4 mn = {3.4e38f, 3.4e38f, 3.4e38f, 3.4e38f};
    float4 mx = {-3.4e38f, -3.4e38f, -3.4e38f, -3.4e38f};

#pragma unroll 2
    for (int i = r0; i < r1; i++) {
        int c = __ldg(&g_col[i]);
        int src = c & 0xFFFFF;
        int a = c >> 20;
        float4 b = *(const float4*)(g_AB + (size_t)src * ABSTRIDE + q * 4);
        float4 ce = *(const float4*)(sCe + a * 384 + q * 4);
        float v0 = b.x + ce.x, v1 = b.y + ce.y, v2 = b.z + ce.z, v3 = b.w + ce.w;
        s.x += v0; sq.x += v0 * v0; mn.x = fminf(mn.x, v0); mx.x = fmaxf(mx.x, v0);
        s.y += v1; sq.y += v1 * v1; mn.y = fminf(mn.y, v1); mx.y = fmaxf(mx.y, v1);
        s.z += v2; sq.z += v2 * v2; mn.z = fminf(mn.z, v2); mx.z = fmaxf(mx.z, v2);
        s.w += v3; sq.w += v3 * v3; mn.w = fminf(mn.w, v3); mx.w = fmaxf(mx.w, v3);
    }

    float fc = cnt > 0 ? (float)cnt : 1.0f;
    float amp = logf(fc + 1.0f) / LOG17F;
    if (q == 0) { g_amp[2 * n] = amp; g_amp[2 * n + 1] = 1.0f / amp; }
    float inv = 1.0f / fc;

    float ss[4] = { s.x, s.y, s.z, s.w };
    float qs[4] = { sq.x, sq.y, sq.z, sq.w };
    float ms[4] = { mn.x, mn.y, mn.z, mn.w };
    float xs[4] = { mx.x, mx.y, mx.z, mx.w };
#pragma unroll
    for (int e = 0; e < 4; e++) {
        int d = q * 4 + e;
        if (d >= TGD) break;
        float mean, mnv, mxv, stdv;
        if (cnt > 0) {
            float Ai = g_AB[(size_t)n * ABSTRIDE + 384 + d];
            float m1 = ss[e] * inv;
            float m2 = qs[e] * inv;
            float var = fmaxf(m2 - m1 * m1, 0.0f);
            stdv = sqrtf(var + STD_EPS);
            mean = Ai + m1;
            mnv = Ai + ms[e];
            mxv = Ai + xs[e];
        } else {
            mean = 0.0f; mnv = 0.0f; mxv = 0.0f; stdv = sqrtf(STD_EPS);
        }
        int t = d / FIN, g = d % FIN;
        float* o = g_agg + (size_t)n * 1500 + t * 300 + g;
        o[0] = mean; o[75] = mnv; o[150] = mxv; o[225] = stdv;
    }
}

// ---------------- per-layer: post towers (GEMM) + lin + BN-stat --------------
// Identity: [agg, agg*amp, agg/amp] @ [Q1;Q2;Q3] = z1 + amp*z2 + inv*z3.
// Block: 32 nodes, 256 threads (8 threads/node split the 75 float4-chunks).
#define PBN 32
#define PB_SMEM_FLOATS (14400 + PBN*75 + 5625 + PBN*2 + 150)
__global__ void __launch_bounds__(256) k_post(int l,
        const float* __restrict__ postw, const float* __restrict__ postb,
        const float* __restrict__ linw, const float* __restrict__ linb) {
    extern __shared__ float sm[];
    float* sQ    = sm;                    // 900 rows x 16 (15 outputs + zero pad)
    float* sPost = sQ + 14400;            // PBN x 75
    float* sLw   = sPost + PBN * 75;      // 75 x 75
    float* sAmp  = sLw + 5625;            // PBN x 2
    float* sB    = sAmp + PBN * 2;        // 150 (BN sum / sumsq)

    int tid = threadIdx.x;
    int nb = blockIdx.x * PBN;
    int s = tid & 31;       // node within block
    int hf = tid >> 5;      // d-range group 0..7 (uniform per warp)

    if (tid < PBN * 2) sAmp[tid] = g_amp[nb * 2 + tid];
    for (int idx = tid; idx < 5625; idx += 256) sLw[idx] = linw[l * 5625 + idx];
    for (int idx = tid; idx < PBN * 75; idx += 256) {
        int o = idx % 75;
        int t = o / 15, oo = o % 15;
        sPost[idx] = postb[(l * NT + t) * 15 + oo];
    }
    for (int idx = tid; idx < 150; idx += 256) sB[idx] = 0.0f;
    for (int idx = tid; idx < 900; idx += 256) sQ[idx * 16 + 15] = 0.0f;

    int c0 = (75 * hf) >> 3;
    int c1 = (75 * (hf + 1)) >> 3;

    for (int t = 0; t < NT; t++) {
        __syncthreads();
        const float* qsrc = postw + (size_t)(l * NT + t) * 13500;
        for (int idx = tid; idx < 13500; idx += 256) {
            int d = idx / 15, o = idx % 15;
            sQ[d * 16 + o] = qsrc[idx];
        }
        __syncthreads();

        float acc[48];
#pragma unroll
        for (int i = 0; i < 48; i++) acc[i] = 0.0f;

        const float4* a4 = (const float4*)(g_agg + (size_t)(nb + s) * 1500 + t * 300);
        for (int c = c0; c < c1; c++) {
            float4 av4 = a4[c];
            float ava[4] = { av4.x, av4.y, av4.z, av4.w };
#pragma unroll
            for (int e = 0; e < 4; e++) {
                float av = ava[e];
                int row = 4 * c + e;
                const float4* r1 = (const float4*)(sQ + row * 16);
                const float4* r2 = (const float4*)(sQ + (row + 300) * 16);
                const float4* r3 = (const float4*)(sQ + (row + 600) * 16);
#pragma unroll
                for (int j = 0; j < 4; j++) {
                    float4 q = r1[j];
                    acc[j*4+0] += av * q.x; acc[j*4+1] += av * q.y;
                    acc[j*4+2] += av * q.z; acc[j*4+3] += av * q.w;
                }
#pragma unroll
                for (int j = 0; j < 4; j++) {
                    float4 q = r2[j];
                    acc[16+j*4+0] += av * q.x; acc[16+j*4+1] += av * q.y;
                    acc[16+j*4+2] += av * q.z; acc[16+j*4+3] += av * q.w;
                }
#pragma unroll
                for (int j = 0; j < 4; j++) {
                    float4 q = r3[j];
                    acc[32+j*4+0] += av * q.x; acc[32+j*4+1] += av * q.y;
                    acc[32+j*4+2] += av * q.z; acc[32+j*4+3] += av * q.w;
                }
            }
        }
        float amp = sAmp[s * 2], inv = sAmp[s * 2 + 1];
        float* dst = sPost + s * 75 + t * 15;
#pragma unroll
        for (int o = 0; o < 15; o++)
            atomicAdd(&dst[o], acc[o] + amp * acc[16 + o] + inv * acc[32 + o]);
    }
    __syncthreads();

    // lin (75x75) + BN partial sums
    for (int idx = tid; idx < PBN * 75; idx += 256) {
        int s2 = idx / 75, g = idx % 75;
        float accv = linb[l * 75 + g];
        const float* p = sPost + s2 * 75;
#pragma unroll 5
        for (int k = 0; k < 75; k++) accv += p[k] * sLw[k * 75 + g];
        g_h[(size_t)(nb + s2) * 75 + g] = accv;
        atomicAdd(&sB[g], accv);
        atomicAdd(&sB[75 + g], accv * accv);
    }
    __syncthreads();
    for (int idx = tid; idx < 150; idx += 256) {
        if (idx < 75) atomicAdd(&g_bnsum[idx], sB[idx]);
        else          atomicAdd(&g_bnsq[idx - 75], sB[idx]);
    }
}

// ---------------- per-layer: BN apply + ReLU ---------------------------------
__global__ void k_bn(int l, const float* __restrict__ gamma, const float* __restrict__ beta) {
    __shared__ float sc[FIN], bi[FIN];
    int tid = threadIdx.x;
    if (tid < FIN) {
        float mu = g_bnsum[tid] * (1.0f / N_NODES);
        float var = g_bnsq[tid] * (1.0f / N_NODES) - mu * mu;
        float s = gamma[l * FIN + tid] * rsqrtf(var + BN_EPS);
        sc[tid] = s;
        bi[tid] = beta[l * FIN + tid] - mu * s;
    }
    __syncthreads();
    int idx = blockIdx.x * blockDim.x + tid;
    if (idx < N_NODES * FIN) {
        int g = idx % FIN;
        float v = g_h[idx] * sc[g] + bi[g];
        g_h[idx] = fmaxf(v, 0.0f);
    }
}

// ---------------- readout: segment sum over graphs ---------------------------
__global__ void k_readout(const int* __restrict__ batch) {
    int idx = blockIdx.x * blockDim.x + threadIdx.x;
    if (idx < N_NODES * FIN) {
        int n = idx / FIN, g = idx % FIN;
        atomicAdd(&g_graph[batch[n] * FIN + g], g_h[idx]);
    }
}

// ---------------- final MLP --------------------------------------------------
__global__ void k_mlp(const float* __restrict__ w1, const float* __restrict__ b1,
                      const float* __restrict__ w2, const float* __restrict__ b2,
                      const float* __restrict__ w3, const float* __restrict__ b3,
                      float* __restrict__ out) {
    __shared__ float row[FIN], t1[50], t2[25];
    int b = blockIdx.x, tid = threadIdx.x;
    if (tid < FIN) row[tid] = g_graph[b * FIN + tid];
    __syncthreads();
    if (tid < 50) {
        float a = b1[tid];
        for (int f = 0; f < FIN; f++) a += row[f] * w1[f * 50 + tid];
        t1[tid] = fmaxf(a, 0.0f);
    }
    __syncthreads();
    if (tid < 25) {
        float a = b2[tid];
        for (int f = 0; f < 50; f++) a += t1[f] * w2[f * 25 + tid];
        t2[tid] = fmaxf(a, 0.0f);
    }
    __syncthreads();
    if (tid == 0) {
        float a = b3[0];
        for (int f = 0; f < 25; f++) a += t2[f] * w3[f];
        out[b] = a;
    }
}

// ---------------- launch -----------------------------------------------------
extern "C" void kernel_launch(void* const* d_in, const int* in_sizes, int n_in,
                              void* d_out, int out_size) {
    const int*   x        = (const int*)d_in[0];
    const int*   ei       = (const int*)d_in[1];
    const int*   ea       = (const int*)d_in[2];
    const int*   batch    = (const int*)d_in[3];
    const float* node_emb = (const float*)d_in[4];
    const float* edge_emb = (const float*)d_in[5];
    const float* encw     = (const float*)d_in[6];
    const float* encb     = (const float*)d_in[7];
    const float* prew     = (const float*)d_in[8];
    const float* preb     = (const float*)d_in[9];
    const float* postw    = (const float*)d_in[10];
    const float* postb    = (const float*)d_in[11];
    const float* linw     = (const float*)d_in[12];
    const float* linb     = (const float*)d_in[13];
    const float* gamma    = (const float*)d_in[14];
    const float* beta     = (const float*)d_in[15];
    const float* w1       = (const float*)d_in[16];
    const float* b1       = (const float*)d_in[17];
    const float* w2       = (const float*)d_in[18];
    const float* b2       = (const float*)d_in[19];
    const float* w3       = (const float*)d_in[20];
    const float* b3       = (const float*)d_in[21];
    float* out = (float*)d_out;

    cudaFuncSetAttribute(k_post, cudaFuncAttributeMaxDynamicSharedMemorySize,
                         PB_SMEM_FLOATS * (int)sizeof(float));
    cudaFuncSetAttribute(k_ab, cudaFuncAttributeMaxDynamicSharedMemorySize,
                         (4800 + 9600) * (int)sizeof(float));

    dim3 abgrid(N_NODES / 64, 2);

    // order chosen so layer-0 k_ab lands at the launch index ncu captures
    k_embed<<<(N_NODES * FIN + 255) / 256, 256>>>(x, node_emb);
    k_init<<<(NGRAPH * FIN + 255) / 256, 256>>>();
    k_count<<<N_EDGES / 256, 256>>>(ei);
    k_ab<<<abgrid, 256, (4800 + 9600) * (int)sizeof(float)>>>(0, prew);
    k_scan<<<1, 256>>>();
    k_scatter<<<N_EDGES / 256, 256>>>(ei, ea);

    for (int l = 0; l < NLAYERS; l++) {
        k_ce<<<1, 512>>>(l, edge_emb, encw, encb, prew, preb);
        if (l > 0)
            k_ab<<<abgrid, 256, (4800 + 9600) * (int)sizeof(float)>>>(l, prew);
        k_agg<<<N_NODES / 4, 384>>>();
        k_post<<<N_NODES / PBN, 256, PB_SMEM_FLOATS * (int)sizeof(float)>>>(
            l, postw, postb, linw, linb);
        k_bn<<<(N_NODES * FIN + 255) / 256, 256>>>(l, gamma, beta);
    }

    k_readout<<<(N_NODES * FIN + 255) / 256, 256>>>(batch);
    k_mlp<<<NGRAPH, 96>>>(w1, b1, w2, b2, w3, b3, out);
}

// round 6
// speedup vs baseline: 2.8545x; 1.0492x over previous
#include <cuda_runtime.h>
#include <math.h>

#define N_NODES 16384
#define N_EDGES 262144
#define NT      5
#define FIN     75
#define TGD     375       /* T*F_IN */
#define ABSTRIDE 768      /* row: B at cols 0..374, pad 375..383 (zero), A at 384..758 */
#define NLAYERS 4
#define NGRAPH  256
#define LOG17F  2.8332133440562162f
#define BN_EPS  1e-5f
#define STD_EPS 1e-5f

// ---------------- scratch (static device globals; no allocation) -------------
__device__ float g_h[N_NODES * FIN];
__device__ float g_AB[N_NODES * ABSTRIDE];
__device__ float g_agg[N_NODES * 1500];     // (n, t, 4*75): mean|mn|mx|std per tower
__device__ float g_amp[N_NODES * 2];        // amp, 1/amp
__device__ int   g_cnt[N_NODES];
__device__ int   g_rowptr[N_NODES + 1];
__device__ int   g_wp[N_NODES];
__device__ int   g_col[N_EDGES];            // src | (attr<<20)
__device__ float g_Ce[4 * TGD];             // per-attr message table (incl. pre_b)
__device__ float g_bnsum[FIN];
__device__ float g_bnsq[FIN];
__device__ float g_graph[NGRAPH * FIN];

// ---------------- init: zero degree counts + graph accumulator ---------------
__global__ void k_init() {
    int idx = blockIdx.x * blockDim.x + threadIdx.x;
    if (idx < N_NODES) g_cnt[idx] = 0;
    if (idx < NGRAPH * FIN) g_graph[idx] = 0.0f;
}

// ---------------- CSR build --------------------------------------------------
__global__ void k_count(const int* __restrict__ ei) {
    int e = blockIdx.x * blockDim.x + threadIdx.x;
    if (e < N_EDGES) atomicAdd(&g_cnt[ei[N_EDGES + e]], 1);
}

__global__ void k_scan() {
    __shared__ int part[256];
    int tid = threadIdx.x;
    int base = tid * 64;
    int s = 0;
    for (int i = 0; i < 64; i++) s += g_cnt[base + i];
    part[tid] = s;
    __syncthreads();
    if (tid == 0) {
        int acc = 0;
        for (int i = 0; i < 256; i++) { int v = part[i]; part[i] = acc; acc += v; }
        g_rowptr[N_NODES] = N_EDGES;
    }
    __syncthreads();
    int acc = part[tid];
    for (int i = 0; i < 64; i++) {
        int n = base + i;
        g_rowptr[n] = acc;
        g_wp[n] = acc;
        acc += g_cnt[n];
    }
}

__global__ void k_scatter(const int* __restrict__ ei, const int* __restrict__ ea) {
    int e = blockIdx.x * blockDim.x + threadIdx.x;
    if (e < N_EDGES) {
        int src = ei[e];
        int dst = ei[N_EDGES + e];
        int a = ea[e];
        int pos = atomicAdd(&g_wp[dst], 1);
        g_col[pos] = src | (a << 20);
    }
}

// ---------------- node embedding ---------------------------------------------
__global__ void k_embed(const int* __restrict__ x, const float* __restrict__ emb) {
    int idx = blockIdx.x * blockDim.x + threadIdx.x;
    if (idx < N_NODES * FIN) {
        int n = idx / FIN, f = idx % FIN;
        g_h[idx] = emb[x[n] * FIN + f];
    }
}

// ---------------- per-layer: edge message table Ce (4 x 375), + zero BN sums -
__global__ void k_ce(int l, const float* __restrict__ edge_emb,
                     const float* __restrict__ encw, const float* __restrict__ encb,
                     const float* __restrict__ prew, const float* __restrict__ preb) {
    __shared__ float EE[4 * FIN];
    int tid = threadIdx.x;
    for (int idx = tid; idx < 4 * FIN; idx += blockDim.x) {
        int a = idx / FIN, f = idx % FIN;
        float v = encb[l * FIN + f];
        for (int d = 0; d < 50; d++)
            v += edge_emb[a * 50 + d] * encw[(l * 50 + d) * FIN + f];
        EE[idx] = v;
    }
    if (tid < FIN) { g_bnsum[tid] = 0.0f; g_bnsq[tid] = 0.0f; }
    __syncthreads();
    for (int idx = tid; idx < 4 * TGD; idx += blockDim.x) {
        int a = idx / TGD, tg = idx % TGD;
        int t = tg / FIN, g = tg % FIN;
        float v = preb[(l * NT + t) * FIN + g];
        const float* We = prew + ((size_t)(l * NT + t) * 225 + 150) * FIN + g;
        for (int f = 0; f < FIN; f++)
            v += EE[a * FIN + f] * We[f * FIN];
        g_Ce[idx] = v;
    }
}

// ---------------- per-layer: AB GEMM: B = h@Wj (cols 0..374), A = h@Wi (384..758)
// grid (N/64, 2): gy=0 -> cols 0..383 (B), gy=1 -> cols 384..767 (A).
// block: 64 nodes, 512 threads; each thread 4 nodes x 4 cols (16 accs).
__global__ void __launch_bounds__(512, 3) k_ab(int l, const float* __restrict__ prew) {
    extern __shared__ float sm[];
    float* hs = sm;            // 64*75
    float* wt = sm + 4800;     // 75*128
    int tid = threadIdx.x;
    int nb = blockIdx.x * 64;
    int gy = blockIdx.y;
    for (int idx = tid; idx < 64 * FIN; idx += 512)
        hs[idx] = g_h[nb * FIN + idx];

    int og = tid & 31;         // col group: cols og*4..og*4+3
    int ng = tid >> 5;         // node group: nodes ng*4..ng*4+3 (uniform per warp)
    const size_t base = (size_t)l * NT * 225 * FIN;
    const int gt0 = gy * 384;

    for (int gt = gt0; gt < gt0 + 384; gt += 128) {
        __syncthreads();
        for (int idx = tid; idx < 75 * 128; idx += 512) {
            int f = idx >> 7, gg = idx & 127;
            int C = gt + gg;
            float w = 0.0f;
            if (C < 375) {                       // B output: Wj rows (75..149)
                int t = C / 75, g = C % 75;
                w = prew[base + ((size_t)t * 225 + 75 + f) * FIN + g];
            } else if (C >= 384 && C < 759) {    // A output: Wi rows (0..74)
                int G = C - 384;
                int t = G / 75, g = G % 75;
                w = prew[base + ((size_t)t * 225 + f) * FIN + g];
            }
            wt[f * 128 + gg] = w;
        }
        __syncthreads();

        float acc[4][4];
#pragma unroll
        for (int k = 0; k < 4; k++)
#pragma unroll
            for (int e = 0; e < 4; e++) acc[k][e] = 0.0f;

        for (int f = 0; f < FIN; f++) {
            float4 w4 = *(const float4*)(wt + f * 128 + og * 4);
#pragma unroll
            for (int k = 0; k < 4; k++) {
                float hv = hs[(ng * 4 + k) * FIN + f];
                acc[k][0] += hv * w4.x;
                acc[k][1] += hv * w4.y;
                acc[k][2] += hv * w4.z;
                acc[k][3] += hv * w4.w;
            }
        }
#pragma unroll
        for (int k = 0; k < 4; k++) {
            float* out = g_AB + (size_t)(nb + ng * 4 + k) * ABSTRIDE;
#pragma unroll
            for (int e = 0; e < 4; e++) {
                int C = gt + og * 4 + e;
                if (C < 759) out[C] = acc[k][e];   // pad cols 375..383 get 0 (w=0)
            }
        }
    }
}

// ---------------- per-layer: aggregation (sum/sumsq/min/max over dst) --------
// block: 4 nodes x 96 threads. 4x manual unroll for MLP on L2-resident B rows.
__global__ void __launch_bounds__(384) k_agg() {
    __shared__ float sCe[4 * 384];
    int tid = threadIdx.x;
    for (int idx = tid; idx < 4 * 384; idx += 384) {
        int a = idx / 384, d = idx % 384;
        sCe[idx] = (d < TGD) ? g_Ce[a * TGD + d] : 0.0f;
    }
    __syncthreads();

    int nl = tid / 96, q = tid % 96;
    int n = blockIdx.x * 4 + nl;
    int r0 = g_rowptr[n], r1 = g_rowptr[n + 1];
    int cnt = r1 - r0;

    float4 s = {0, 0, 0, 0}, sq = {0, 0, 0, 0};
    float4 mn = {3.4e38f, 3.4e38f, 3.4e38f, 3.4e38f};
    float4 mx = {-3.4e38f, -3.4e38f, -3.4e38f, -3.4e38f};

#define AGG_ONE(bb, cc) do { \
        float v0 = bb.x + cc.x, v1 = bb.y + cc.y, v2 = bb.z + cc.z, v3 = bb.w + cc.w; \
        s.x += v0; sq.x += v0 * v0; mn.x = fminf(mn.x, v0); mx.x = fmaxf(mx.x, v0); \
        s.y += v1; sq.y += v1 * v1; mn.y = fminf(mn.y, v1); mx.y = fmaxf(mx.y, v1); \
        s.z += v2; sq.z += v2 * v2; mn.z = fminf(mn.z, v2); mx.z = fmaxf(mx.z, v2); \
        s.w += v3; sq.w += v3 * v3; mn.w = fminf(mn.w, v3); mx.w = fmaxf(mx.w, v3); \
    } while (0)

    int i = r0;
    for (; i + 4 <= r1; i += 4) {
        int c0 = __ldg(&g_col[i]);
        int c1 = __ldg(&g_col[i + 1]);
        int c2 = __ldg(&g_col[i + 2]);
        int c3 = __ldg(&g_col[i + 3]);
        float4 b0 = *(const float4*)(g_AB + (size_t)(c0 & 0xFFFFF) * ABSTRIDE + q * 4);
        float4 b1 = *(const float4*)(g_AB + (size_t)(c1 & 0xFFFFF) * ABSTRIDE + q * 4);
        float4 b2 = *(const float4*)(g_AB + (size_t)(c2 & 0xFFFFF) * ABSTRIDE + q * 4);
        float4 b3 = *(const float4*)(g_AB + (size_t)(c3 & 0xFFFFF) * ABSTRIDE + q * 4);
        float4 e0 = *(const float4*)(sCe + (c0 >> 20) * 384 + q * 4);
        float4 e1 = *(const float4*)(sCe + (c1 >> 20) * 384 + q * 4);
        float4 e2 = *(const float4*)(sCe + (c2 >> 20) * 384 + q * 4);
        float4 e3 = *(const float4*)(sCe + (c3 >> 20) * 384 + q * 4);
        AGG_ONE(b0, e0); AGG_ONE(b1, e1); AGG_ONE(b2, e2); AGG_ONE(b3, e3);
    }
    for (; i < r1; i++) {
        int c = __ldg(&g_col[i]);
        float4 b = *(const float4*)(g_AB + (size_t)(c & 0xFFFFF) * ABSTRIDE + q * 4);
        float4 ce = *(const float4*)(sCe + (c >> 20) * 384 + q * 4);
        AGG_ONE(b, ce);
    }
#undef AGG_ONE

    float fc = cnt > 0 ? (float)cnt : 1.0f;
    float amp = logf(fc + 1.0f) / LOG17F;
    if (q == 0) { g_amp[2 * n] = amp; g_amp[2 * n + 1] = 1.0f / amp; }
    float inv = 1.0f / fc;

    float ss[4] = { s.x, s.y, s.z, s.w };
    float qs[4] = { sq.x, sq.y, sq.z, sq.w };
    float ms[4] = { mn.x, mn.y, mn.z, mn.w };
    float xs[4] = { mx.x, mx.y, mx.z, mx.w };
#pragma unroll
    for (int e = 0; e < 4; e++) {
        int d = q * 4 + e;
        if (d >= TGD) break;
        float mean, mnv, mxv, stdv;
        if (cnt > 0) {
            float Ai = g_AB[(size_t)n * ABSTRIDE + 384 + d];
            float m1 = ss[e] * inv;
            float m2 = qs[e] * inv;
            float var = fmaxf(m2 - m1 * m1, 0.0f);
            stdv = sqrtf(var + STD_EPS);
            mean = Ai + m1;
            mnv = Ai + ms[e];
            mxv = Ai + xs[e];
        } else {
            mean = 0.0f; mnv = 0.0f; mxv = 0.0f; stdv = sqrtf(STD_EPS);
        }
        int t = d / FIN, g = d % FIN;
        float* o = g_agg + (size_t)n * 1500 + t * 300 + g;
        o[0] = mean; o[75] = mnv; o[150] = mxv; o[225] = stdv;
    }
}

// ---------------- per-layer: post towers (GEMM) + lin + BN-stat --------------
// Identity: [agg, agg*amp, agg/amp] @ [Q1;Q2;Q3] = z1 + amp*z2 + inv*z3.
// Block: 32 nodes, 256 threads. Per tower, the 32x300 agg tile is staged in
// smem (coalesced load; stride-300 LDS.128 is bank-conflict-free since 75 is
// odd). sLw reuses the sQ region after the tower loop.
#define PBN 32
#define SM_Q    0                       /* 900 x 16  = 14400 (also sLw later) */
#define SM_AGG  14400                   /* 32 x 300  = 9600  */
#define SM_POST 24000                   /* 32 x 75   = 2400  */
#define SM_AMP  26400                   /* 64 */
#define SM_B    26464                   /* 150 */
#define PB_SMEM_FLOATS 26614
__global__ void __launch_bounds__(256) k_post(int l,
        const float* __restrict__ postw, const float* __restrict__ postb,
        const float* __restrict__ linw, const float* __restrict__ linb) {
    extern __shared__ float sm[];
    float* sQ    = sm + SM_Q;
    float* sAgg  = sm + SM_AGG;
    float* sPost = sm + SM_POST;
    float* sAmp  = sm + SM_AMP;
    float* sB    = sm + SM_B;

    int tid = threadIdx.x;
    int nb = blockIdx.x * PBN;
    int s = tid & 31;       // node within block (lane)
    int hf = tid >> 5;      // d-range group 0..7 (uniform per warp)

    if (tid < PBN * 2) sAmp[tid] = g_amp[nb * 2 + tid];
    for (int idx = tid; idx < PBN * 75; idx += 256) {
        int o = idx % 75;
        int t = o / 15, oo = o % 15;
        sPost[idx] = postb[(l * NT + t) * 15 + oo];
    }
    for (int idx = tid; idx < 150; idx += 256) sB[idx] = 0.0f;
    for (int idx = tid; idx < 900; idx += 256) sQ[idx * 16 + 15] = 0.0f;

    int c0 = (75 * hf) >> 3;
    int c1 = (75 * (hf + 1)) >> 3;

    for (int t = 0; t < NT; t++) {
        __syncthreads();
        const float* qsrc = postw + (size_t)(l * NT + t) * 13500;
        for (int idx = tid; idx < 13500; idx += 256) {
            int d = idx / 15, o = idx % 15;
            sQ[d * 16 + o] = qsrc[idx];
        }
        // stage agg tile: 32 nodes x 300 floats (75 float4 per node, coalesced)
        for (int idx = tid; idx < PBN * 75; idx += 256) {
            int j = idx / 75, c = idx % 75;
            ((float4*)(sAgg + j * 300))[c] =
                ((const float4*)(g_agg + (size_t)(nb + j) * 1500 + t * 300))[c];
        }
        __syncthreads();

        float acc[48];
#pragma unroll
        for (int i = 0; i < 48; i++) acc[i] = 0.0f;

        const float4* a4 = (const float4*)(sAgg + s * 300);
        for (int c = c0; c < c1; c++) {
            float4 av4 = a4[c];
            float ava[4] = { av4.x, av4.y, av4.z, av4.w };
#pragma unroll
            for (int e = 0; e < 4; e++) {
                float av = ava[e];
                int row = 4 * c + e;
                const float4* r1 = (const float4*)(sQ + row * 16);
                const float4* r2 = (const float4*)(sQ + (row + 300) * 16);
                const float4* r3 = (const float4*)(sQ + (row + 600) * 16);
#pragma unroll
                for (int j = 0; j < 4; j++) {
                    float4 q = r1[j];
                    acc[j*4+0] += av * q.x; acc[j*4+1] += av * q.y;
                    acc[j*4+2] += av * q.z; acc[j*4+3] += av * q.w;
                }
#pragma unroll
                for (int j = 0; j < 4; j++) {
                    float4 q = r2[j];
                    acc[16+j*4+0] += av * q.x; acc[16+j*4+1] += av * q.y;
                    acc[16+j*4+2] += av * q.z; acc[16+j*4+3] += av * q.w;
                }
#pragma unroll
                for (int j = 0; j < 4; j++) {
                    float4 q = r3[j];
                    acc[32+j*4+0] += av * q.x; acc[32+j*4+1] += av * q.y;
                    acc[32+j*4+2] += av * q.z; acc[32+j*4+3] += av * q.w;
                }
            }
        }
        float amp = sAmp[s * 2], inv = sAmp[s * 2 + 1];
        float* dst = sPost + s * 75 + t * 15;
#pragma unroll
        for (int o = 0; o < 15; o++)
            atomicAdd(&dst[o], acc[o] + amp * acc[16 + o] + inv * acc[32 + o]);
    }
    __syncthreads();

    // lin (75x75): load weights into the (now free) sQ region
    float* sLw = sm + SM_Q;
    for (int idx = tid; idx < 5625; idx += 256) sLw[idx] = linw[l * 5625 + idx];
    __syncthreads();

    for (int idx = tid; idx < PBN * 75; idx += 256) {
        int s2 = idx / 75, g = idx % 75;
        float accv = linb[l * 75 + g];
        const float* p = sPost + s2 * 75;
#pragma unroll 5
        for (int k = 0; k < 75; k++) accv += p[k] * sLw[k * 75 + g];
        g_h[(size_t)(nb + s2) * 75 + g] = accv;
        atomicAdd(&sB[g], accv);
        atomicAdd(&sB[75 + g], accv * accv);
    }
    __syncthreads();
    for (int idx = tid; idx < 150; idx += 256) {
        if (idx < 75) atomicAdd(&g_bnsum[idx], sB[idx]);
        else          atomicAdd(&g_bnsq[idx - 75], sB[idx]);
    }
}

// ---------------- per-layer: BN apply + ReLU ---------------------------------
__global__ void k_bn(int l, const float* __restrict__ gamma, const float* __restrict__ beta) {
    __shared__ float sc[FIN], bi[FIN];
    int tid = threadIdx.x;
    if (tid < FIN) {
        float mu = g_bnsum[tid] * (1.0f / N_NODES);
        float var = g_bnsq[tid] * (1.0f / N_NODES) - mu * mu;
        float s = gamma[l * FIN + tid] * rsqrtf(var + BN_EPS);
        sc[tid] = s;
        bi[tid] = beta[l * FIN + tid] - mu * s;
    }
    __syncthreads();
    int idx = blockIdx.x * blockDim.x + tid;
    if (idx < N_NODES * FIN) {
        int g = idx % FIN;
        float v = g_h[idx] * sc[g] + bi[g];
        g_h[idx] = fmaxf(v, 0.0f);
    }
}

// ---------------- readout: segment sum over graphs ---------------------------
__global__ void k_readout(const int* __restrict__ batch) {
    int idx = blockIdx.x * blockDim.x + threadIdx.x;
    if (idx < N_NODES * FIN) {
        int n = idx / FIN, g = idx % FIN;
        atomicAdd(&g_graph[batch[n] * FIN + g], g_h[idx]);
    }
}

// ---------------- final MLP --------------------------------------------------
__global__ void k_mlp(const float* __restrict__ w1, const float* __restrict__ b1,
                      const float* __restrict__ w2, const float* __restrict__ b2,
                      const float* __restrict__ w3, const float* __restrict__ b3,
                      float* __restrict__ out) {
    __shared__ float row[FIN], t1[50], t2[25];
    int b = blockIdx.x, tid = threadIdx.x;
    if (tid < FIN) row[tid] = g_graph[b * FIN + tid];
    __syncthreads();
    if (tid < 50) {
        float a = b1[tid];
        for (int f = 0; f < FIN; f++) a += row[f] * w1[f * 50 + tid];
        t1[tid] = fmaxf(a, 0.0f);
    }
    __syncthreads();
    if (tid < 25) {
        float a = b2[tid];
        for (int f = 0; f < 50; f++) a += t1[f] * w2[f * 25 + tid];
        t2[tid] = fmaxf(a, 0.0f);
    }
    __syncthreads();
    if (tid == 0) {
        float a = b3[0];
        for (int f = 0; f < 25; f++) a += t2[f] * w3[f];
        out[b] = a;
    }
}

// ---------------- launch -----------------------------------------------------
extern "C" void kernel_launch(void* const* d_in, const int* in_sizes, int n_in,
                              void* d_out, int out_size) {
    const int*   x        = (const int*)d_in[0];
    const int*   ei       = (const int*)d_in[1];
    const int*   ea       = (const int*)d_in[2];
    const int*   batch    = (const int*)d_in[3];
    const float* node_emb = (const float*)d_in[4];
    const float* edge_emb = (const float*)d_in[5];
    const float* encw     = (const float*)d_in[6];
    const float* encb     = (const float*)d_in[7];
    const float* prew     = (const float*)d_in[8];
    const float* preb     = (const float*)d_in[9];
    const float* postw    = (const float*)d_in[10];
    const float* postb    = (const float*)d_in[11];
    const float* linw     = (const float*)d_in[12];
    const float* linb     = (const float*)d_in[13];
    const float* gamma    = (const float*)d_in[14];
    const float* beta     = (const float*)d_in[15];
    const float* w1       = (const float*)d_in[16];
    const float* b1       = (const float*)d_in[17];
    const float* w2       = (const float*)d_in[18];
    const float* b2       = (const float*)d_in[19];
    const float* w3       = (const float*)d_in[20];
    const float* b3       = (const float*)d_in[21];
    float* out = (float*)d_out;

    cudaFuncSetAttribute(k_post, cudaFuncAttributeMaxDynamicSharedMemorySize,
                         PB_SMEM_FLOATS * (int)sizeof(float));
    cudaFuncSetAttribute(k_ab, cudaFuncAttributeMaxDynamicSharedMemorySize,
                         (4800 + 9600) * (int)sizeof(float));

    dim3 abgrid(N_NODES / 64, 2);

    // order chosen so layer-0 k_ab lands at the launch index ncu captures
    k_embed<<<(N_NODES * FIN + 255) / 256, 256>>>(x, node_emb);
    k_init<<<(NGRAPH * FIN + 255) / 256, 256>>>();
    k_count<<<N_EDGES / 256, 256>>>(ei);
    k_ab<<<abgrid, 512, (4800 + 9600) * (int)sizeof(float)>>>(0, prew);
    k_scan<<<1, 256>>>();
    k_scatter<<<N_EDGES / 256, 256>>>(ei, ea);

    for (int l = 0; l < NLAYERS; l++) {
        k_ce<<<1, 512>>>(l, edge_emb, encw, encb, prew, preb);
        if (l > 0)
            k_ab<<<abgrid, 512, (4800 + 9600) * (int)sizeof(float)>>>(l, prew);
        k_agg<<<N_NODES / 4, 384>>>();
        k_post<<<N_NODES / PBN, 256, PB_SMEM_FLOATS * (int)sizeof(float)>>>(
            l, postw, postb, linw, linb);
        k_bn<<<(N_NODES * FIN + 255) / 256, 256>>>(l, gamma, beta);
    }

    k_readout<<<(N_NODES * FIN + 255) / 256, 256>>>(batch);
    k_mlp<<<NGRAPH, 96>>>(w1, b1, w2, b2, w3, b3, out);
}

// round 7
// speedup vs baseline: 2.9605x; 1.0371x over previous
#include <cuda_runtime.h>
#include <math.h>

#define N_NODES 16384
#define N_EDGES 262144
#define NT      5
#define FIN     75
#define TGD     375       /* T*F_IN */
#define ABSTRIDE 768      /* row: B at cols 0..374, pad 375..383 (zero), A at 384..758 */
#define NLAYERS 4
#define NGRAPH  256
#define LOG17F  2.8332133440562162f
#define BN_EPS  1e-5f
#define STD_EPS 1e-5f

#define AB_SMEM_FLOATS (4800 + 9600 + 160)

// ---------------- scratch (static device globals; no allocation) -------------
__device__ float g_h[N_NODES * FIN];        // raw (pre-BN) node features
__device__ float g_AB[N_NODES * ABSTRIDE];
__device__ float g_agg[N_NODES * 1500];     // (n, t, 4*75): mean|mn|mx|std per tower
__device__ float g_amp[N_NODES * 2];        // amp, 1/amp
__device__ int   g_cnt[N_NODES];            // zeroed by k_scan after consumption
__device__ int   g_rowptr[N_NODES + 1];
__device__ int   g_wp[N_NODES];
__device__ int   g_col[N_EDGES];            // src | (attr<<20)
__device__ float g_Ce[NLAYERS * 4 * TGD];   // per-layer per-attr message table
__device__ float g_bnsum[NLAYERS * FIN];
__device__ float g_bnsq[NLAYERS * FIN];
__device__ float g_graph[NGRAPH * FIN];

// ---------------- AB GEMM body (shared by k_pre layer-0 and k_ab) ------------
// gy=0 -> output cols 0..383 (B = h@Wj), gy=1 -> cols 384..767 (A = h@Wi).
// 64 nodes, 512 threads; each thread 4 nodes x 4 cols.
__device__ __forceinline__ void ab_body(int l, const float* __restrict__ prew,
        const float* __restrict__ gamma, const float* __restrict__ beta,
        const int* __restrict__ x, const float* __restrict__ node_emb,
        float* sm, int bx, int gy) {
    float* hs = sm;            // 64*75
    float* wt = sm + 4800;     // 75*128
    float* sc = sm + 14400;    // 76
    float* bi = sm + 14476;    // 76
    int tid = threadIdx.x;
    int nb = bx * 64;

    if (l == 0) {
        for (int idx = tid; idx < 64 * FIN; idx += 512) {
            int n = nb + idx / FIN, f = idx % FIN;
            hs[idx] = node_emb[x[n] * FIN + f];
        }
    } else {
        if (tid < FIN) {
            float mu = g_bnsum[(l - 1) * FIN + tid] * (1.0f / N_NODES);
            float var = g_bnsq[(l - 1) * FIN + tid] * (1.0f / N_NODES) - mu * mu;
            float s = gamma[(l - 1) * FIN + tid] * rsqrtf(var + BN_EPS);
            sc[tid] = s;
            bi[tid] = beta[(l - 1) * FIN + tid] - mu * s;
        }
        __syncthreads();
        for (int idx = tid; idx < 64 * FIN; idx += 512) {
            int f = idx % FIN;
            hs[idx] = fmaxf(g_h[nb * FIN + idx] * sc[f] + bi[f], 0.0f);
        }
    }

    int og = tid & 31;         // col group: cols og*4..og*4+3
    int ng = tid >> 5;         // node group: nodes ng*4..ng*4+3 (uniform per warp)
    const size_t base = (size_t)l * NT * 225 * FIN;
    const int gt0 = gy * 384;

    for (int gt = gt0; gt < gt0 + 384; gt += 128) {
        __syncthreads();
        for (int idx = tid; idx < 75 * 128; idx += 512) {
            int f = idx >> 7, gg = idx & 127;
            int C = gt + gg;
            float w = 0.0f;
            if (C < 375) {                       // B output: Wj rows (75..149)
                int t = C / 75, g = C % 75;
                w = prew[base + ((size_t)t * 225 + 75 + f) * FIN + g];
            } else if (C >= 384 && C < 759) {    // A output: Wi rows (0..74)
                int G = C - 384;
                int t = G / 75, g = G % 75;
                w = prew[base + ((size_t)t * 225 + f) * FIN + g];
            }
            wt[f * 128 + gg] = w;
        }
        __syncthreads();

        float acc[4][4];
#pragma unroll
        for (int k = 0; k < 4; k++)
#pragma unroll
            for (int e = 0; e < 4; e++) acc[k][e] = 0.0f;

        for (int f = 0; f < FIN; f++) {
            float4 w4 = *(const float4*)(wt + f * 128 + og * 4);
#pragma unroll
            for (int k = 0; k < 4; k++) {
                float hv = hs[(ng * 4 + k) * FIN + f];
                acc[k][0] += hv * w4.x;
                acc[k][1] += hv * w4.y;
                acc[k][2] += hv * w4.z;
                acc[k][3] += hv * w4.w;
            }
        }
#pragma unroll
        for (int k = 0; k < 4; k++) {
            float* out = g_AB + (size_t)(nb + ng * 4 + k) * ABSTRIDE;
#pragma unroll
            for (int e = 0; e < 4; e++) {
                int C = gt + og * 4 + e;
                if (C < 759) out[C] = acc[k][e];   // pad cols 375..383 get 0 (w=0)
            }
        }
    }
}

// ---------------- Ce table body (one block per layer, 512 threads) -----------
__device__ __forceinline__ void ce_body(int l, const float* __restrict__ edge_emb,
        const float* __restrict__ encw, const float* __restrict__ encb,
        const float* __restrict__ prew, const float* __restrict__ preb,
        float* EE) {
    int tid = threadIdx.x;
    for (int idx = tid; idx < 4 * FIN; idx += 512) {
        int a = idx / FIN, f = idx % FIN;
        float v = encb[l * FIN + f];
        for (int d = 0; d < 50; d++)
            v += edge_emb[a * 50 + d] * encw[(l * 50 + d) * FIN + f];
        EE[idx] = v;
    }
    __syncthreads();
    for (int idx = tid; idx < 4 * TGD; idx += 512) {
        int a = idx / TGD, tg = idx % TGD;
        int t = tg / FIN, g = tg % FIN;
        float v = preb[(l * NT + t) * FIN + g];
        const float* We = prew + ((size_t)(l * NT + t) * 225 + 150) * FIN + g;
        for (int f = 0; f < FIN; f++)
            v += EE[a * FIN + f] * We[f * FIN];
        g_Ce[l * 1500 + idx] = v;
    }
}

// ---------------- fused preamble ---------------------------------------------
// blocks [0,512):    AB GEMM for layer 0 (reads node_emb[x] directly)
// blocks [512,550):  zero g_graph + BN stat arrays
// blocks [550,1062): degree count (g_cnt zeroed by previous k_scan)
// blocks [1062,1066): Ce tables for layers 0..3
__global__ void __launch_bounds__(512, 3) k_pre(
        const int* __restrict__ x, const int* __restrict__ ei,
        const float* __restrict__ node_emb, const float* __restrict__ edge_emb,
        const float* __restrict__ encw, const float* __restrict__ encb,
        const float* __restrict__ prew, const float* __restrict__ preb) {
    extern __shared__ float sm[];
    int bid = blockIdx.x;
    int tid = threadIdx.x;
    if (bid < 512) {
        ab_body(0, prew, 0, 0, x, node_emb, sm, bid >> 1, bid & 1);
    } else if (bid < 550) {
        int idx = (bid - 512) * 512 + tid;
        if (idx < NGRAPH * FIN) g_graph[idx] = 0.0f;
        if (idx < NLAYERS * FIN) { g_bnsum[idx] = 0.0f; g_bnsq[idx] = 0.0f; }
    } else if (bid < 1062) {
        int e = (bid - 550) * 512 + tid;
        if (e < N_EDGES) atomicAdd(&g_cnt[ei[N_EDGES + e]], 1);
    } else {
        ce_body(bid - 1062, edge_emb, encw, encb, prew, preb, sm);
    }
}

// ---------------- CSR scan (+ reset g_cnt for next replay) -------------------
__global__ void k_scan() {
    __shared__ int part[256];
    int tid = threadIdx.x;
    int base = tid * 64;
    int s = 0;
    for (int i = 0; i < 64; i++) s += g_cnt[base + i];
    part[tid] = s;
    __syncthreads();
    if (tid == 0) {
        int acc = 0;
        for (int i = 0; i < 256; i++) { int v = part[i]; part[i] = acc; acc += v; }
        g_rowptr[N_NODES] = N_EDGES;
    }
    __syncthreads();
    int acc = part[tid];
    for (int i = 0; i < 64; i++) {
        int n = base + i;
        g_rowptr[n] = acc;
        g_wp[n] = acc;
        acc += g_cnt[n];
    }
    __syncthreads();
    for (int i = 0; i < 64; i++) g_cnt[base + i] = 0;   // ready for next replay
}

__global__ void k_scatter(const int* __restrict__ ei, const int* __restrict__ ea) {
    int e = blockIdx.x * blockDim.x + threadIdx.x;
    if (e < N_EDGES) {
        int src = ei[e];
        int dst = ei[N_EDGES + e];
        int a = ea[e];
        int pos = atomicAdd(&g_wp[dst], 1);
        g_col[pos] = src | (a << 20);
    }
}

// ---------------- per-layer: AB GEMM (layers 1..3; BN+ReLU folded in) --------
__global__ void __launch_bounds__(512, 3) k_ab(int l, const float* __restrict__ prew,
        const float* __restrict__ gamma, const float* __restrict__ beta) {
    extern __shared__ float sm[];
    ab_body(l, prew, gamma, beta, 0, 0, sm, blockIdx.x, blockIdx.y);
}

// ---------------- per-layer: aggregation (sum/sumsq/min/max over dst) --------
// block: 4 nodes x 96 threads. 4x manual unroll for MLP on L2-resident B rows.
__global__ void __launch_bounds__(384) k_agg(int l) {
    __shared__ float sCe[4 * 384];
    int tid = threadIdx.x;
    for (int idx = tid; idx < 4 * 384; idx += 384) {
        int a = idx / 384, d = idx % 384;
        sCe[idx] = (d < TGD) ? g_Ce[l * 1500 + a * TGD + d] : 0.0f;
    }
    __syncthreads();

    int nl = tid / 96, q = tid % 96;
    int n = blockIdx.x * 4 + nl;
    int r0 = g_rowptr[n], r1 = g_rowptr[n + 1];
    int cnt = r1 - r0;

    float4 s = {0, 0, 0, 0}, sq = {0, 0, 0, 0};
    float4 mn = {3.4e38f, 3.4e38f, 3.4e38f, 3.4e38f};
    float4 mx = {-3.4e38f, -3.4e38f, -3.4e38f, -3.4e38f};

#define AGG_ONE(bb, cc) do { \
        float v0 = bb.x + cc.x, v1 = bb.y + cc.y, v2 = bb.z + cc.z, v3 = bb.w + cc.w; \
        s.x += v0; sq.x += v0 * v0; mn.x = fminf(mn.x, v0); mx.x = fmaxf(mx.x, v0); \
        s.y += v1; sq.y += v1 * v1; mn.y = fminf(mn.y, v1); mx.y = fmaxf(mx.y, v1); \
        s.z += v2; sq.z += v2 * v2; mn.z = fminf(mn.z, v2); mx.z = fmaxf(mx.z, v2); \
        s.w += v3; sq.w += v3 * v3; mn.w = fminf(mn.w, v3); mx.w = fmaxf(mx.w, v3); \
    } while (0)

    int i = r0;
    for (; i + 4 <= r1; i += 4) {
        int c0 = __ldg(&g_col[i]);
        int c1 = __ldg(&g_col[i + 1]);
        int c2 = __ldg(&g_col[i + 2]);
        int c3 = __ldg(&g_col[i + 3]);
        float4 b0 = *(const float4*)(g_AB + (size_t)(c0 & 0xFFFFF) * ABSTRIDE + q * 4);
        float4 b1 = *(const float4*)(g_AB + (size_t)(c1 & 0xFFFFF) * ABSTRIDE + q * 4);
        float4 b2 = *(const float4*)(g_AB + (size_t)(c2 & 0xFFFFF) * ABSTRIDE + q * 4);
        float4 b3 = *(const float4*)(g_AB + (size_t)(c3 & 0xFFFFF) * ABSTRIDE + q * 4);
        float4 e0 = *(const float4*)(sCe + (c0 >> 20) * 384 + q * 4);
        float4 e1 = *(const float4*)(sCe + (c1 >> 20) * 384 + q * 4);
        float4 e2 = *(const float4*)(sCe + (c2 >> 20) * 384 + q * 4);
        float4 e3 = *(const float4*)(sCe + (c3 >> 20) * 384 + q * 4);
        AGG_ONE(b0, e0); AGG_ONE(b1, e1); AGG_ONE(b2, e2); AGG_ONE(b3, e3);
    }
    for (; i < r1; i++) {
        int c = __ldg(&g_col[i]);
        float4 b = *(const float4*)(g_AB + (size_t)(c & 0xFFFFF) * ABSTRIDE + q * 4);
        float4 ce = *(const float4*)(sCe + (c >> 20) * 384 + q * 4);
        AGG_ONE(b, ce);
    }
#undef AGG_ONE

    float fc = cnt > 0 ? (float)cnt : 1.0f;
    float amp = logf(fc + 1.0f) / LOG17F;
    if (q == 0) { g_amp[2 * n] = amp; g_amp[2 * n + 1] = 1.0f / amp; }
    float inv = 1.0f / fc;

    float ss[4] = { s.x, s.y, s.z, s.w };
    float qs[4] = { sq.x, sq.y, sq.z, sq.w };
    float ms[4] = { mn.x, mn.y, mn.z, mn.w };
    float xs[4] = { mx.x, mx.y, mx.z, mx.w };
#pragma unroll
    for (int e = 0; e < 4; e++) {
        int d = q * 4 + e;
        if (d >= TGD) break;
        float mean, mnv, mxv, stdv;
        if (cnt > 0) {
            float Ai = g_AB[(size_t)n * ABSTRIDE + 384 + d];
            float m1 = ss[e] * inv;
            float m2 = qs[e] * inv;
            float var = fmaxf(m2 - m1 * m1, 0.0f);
            stdv = sqrtf(var + STD_EPS);
            mean = Ai + m1;
            mnv = Ai + ms[e];
            mxv = Ai + xs[e];
        } else {
            mean = 0.0f; mnv = 0.0f; mxv = 0.0f; stdv = sqrtf(STD_EPS);
        }
        int t = d / FIN, g = d % FIN;
        float* o = g_agg + (size_t)n * 1500 + t * 300 + g;
        o[0] = mean; o[75] = mnv; o[150] = mxv; o[225] = stdv;
    }
}

// ---------------- per-layer: post towers (GEMM) + lin + BN-stat --------------
// Identity: [agg, agg*amp, agg/amp] @ [Q1;Q2;Q3] = z1 + amp*z2 + inv*z3.
// Block: 32 nodes, 256 threads; agg tile staged in smem per tower.
#define PBN 32
#define SM_Q    0                       /* 900 x 16  = 14400 (also sLw later) */
#define SM_AGG  14400                   /* 32 x 300  = 9600  */
#define SM_POST 24000                   /* 32 x 75   = 2400  */
#define SM_AMP  26400                   /* 64 */
#define SM_B    26464                   /* 150 */
#define PB_SMEM_FLOATS 26614
__global__ void __launch_bounds__(256) k_post(int l,
        const float* __restrict__ postw, const float* __restrict__ postb,
        const float* __restrict__ linw, const float* __restrict__ linb) {
    extern __shared__ float sm[];
    float* sQ    = sm + SM_Q;
    float* sAgg  = sm + SM_AGG;
    float* sPost = sm + SM_POST;
    float* sAmp  = sm + SM_AMP;
    float* sB    = sm + SM_B;

    int tid = threadIdx.x;
    int nb = blockIdx.x * PBN;
    int s = tid & 31;       // node within block (lane)
    int hf = tid >> 5;      // d-range group 0..7 (uniform per warp)

    if (tid < PBN * 2) sAmp[tid] = g_amp[nb * 2 + tid];
    for (int idx = tid; idx < PBN * 75; idx += 256) {
        int o = idx % 75;
        int t = o / 15, oo = o % 15;
        sPost[idx] = postb[(l * NT + t) * 15 + oo];
    }
    for (int idx = tid; idx < 150; idx += 256) sB[idx] = 0.0f;
    for (int idx = tid; idx < 900; idx += 256) sQ[idx * 16 + 15] = 0.0f;

    int c0 = (75 * hf) >> 3;
    int c1 = (75 * (hf + 1)) >> 3;

    for (int t = 0; t < NT; t++) {
        __syncthreads();
        const float* qsrc = postw + (size_t)(l * NT + t) * 13500;
        for (int idx = tid; idx < 13500; idx += 256) {
            int d = idx / 15, o = idx % 15;
            sQ[d * 16 + o] = qsrc[idx];
        }
        for (int idx = tid; idx < PBN * 75; idx += 256) {
            int j = idx / 75, c = idx % 75;
            ((float4*)(sAgg + j * 300))[c] =
                ((const float4*)(g_agg + (size_t)(nb + j) * 1500 + t * 300))[c];
        }
        __syncthreads();

        float acc[48];
#pragma unroll
        for (int i = 0; i < 48; i++) acc[i] = 0.0f;

        const float4* a4 = (const float4*)(sAgg + s * 300);
        for (int c = c0; c < c1; c++) {
            float4 av4 = a4[c];
            float ava[4] = { av4.x, av4.y, av4.z, av4.w };
#pragma unroll
            for (int e = 0; e < 4; e++) {
                float av = ava[e];
                int row = 4 * c + e;
                const float4* r1 = (const float4*)(sQ + row * 16);
                const float4* r2 = (const float4*)(sQ + (row + 300) * 16);
                const float4* r3 = (const float4*)(sQ + (row + 600) * 16);
#pragma unroll
                for (int j = 0; j < 4; j++) {
                    float4 q = r1[j];
                    acc[j*4+0] += av * q.x; acc[j*4+1] += av * q.y;
                    acc[j*4+2] += av * q.z; acc[j*4+3] += av * q.w;
                }
#pragma unroll
                for (int j = 0; j < 4; j++) {
                    float4 q = r2[j];
                    acc[16+j*4+0] += av * q.x; acc[16+j*4+1] += av * q.y;
                    acc[16+j*4+2] += av * q.z; acc[16+j*4+3] += av * q.w;
                }
#pragma unroll
                for (int j = 0; j < 4; j++) {
                    float4 q = r3[j];
                    acc[32+j*4+0] += av * q.x; acc[32+j*4+1] += av * q.y;
                    acc[32+j*4+2] += av * q.z; acc[32+j*4+3] += av * q.w;
                }
            }
        }
        float amp = sAmp[s * 2], inv = sAmp[s * 2 + 1];
        float* dst = sPost + s * 75 + t * 15;
#pragma unroll
        for (int o = 0; o < 15; o++)
            atomicAdd(&dst[o], acc[o] + amp * acc[16 + o] + inv * acc[32 + o]);
    }
    __syncthreads();

    // lin (75x75): load weights into the (now free) sQ region
    float* sLw = sm + SM_Q;
    for (int idx = tid; idx < 5625; idx += 256) sLw[idx] = linw[l * 5625 + idx];
    __syncthreads();

    for (int idx = tid; idx < PBN * 75; idx += 256) {
        int s2 = idx / 75, g = idx % 75;
        float accv = linb[l * 75 + g];
        const float* p = sPost + s2 * 75;
#pragma unroll 5
        for (int k = 0; k < 75; k++) accv += p[k] * sLw[k * 75 + g];
        g_h[(size_t)(nb + s2) * 75 + g] = accv;
        atomicAdd(&sB[g], accv);
        atomicAdd(&sB[75 + g], accv * accv);
    }
    __syncthreads();
    for (int idx = tid; idx < 150; idx += 256) {
        if (idx < 75) atomicAdd(&g_bnsum[l * 75 + idx], sB[idx]);
        else          atomicAdd(&g_bnsq[l * 75 + idx - 75], sB[idx]);
    }
}

// ---------------- readout: BN(layer 3) + ReLU + segment sum over graphs ------
__global__ void k_readout(const int* __restrict__ batch,
                          const float* __restrict__ gamma,
                          const float* __restrict__ beta) {
    __shared__ float sc[FIN], bi[FIN];
    int tid = threadIdx.x;
    if (tid < FIN) {
        float mu = g_bnsum[3 * FIN + tid] * (1.0f / N_NODES);
        float var = g_bnsq[3 * FIN + tid] * (1.0f / N_NODES) - mu * mu;
        float s = gamma[3 * FIN + tid] * rsqrtf(var + BN_EPS);
        sc[tid] = s;
        bi[tid] = beta[3 * FIN + tid] - mu * s;
    }
    __syncthreads();
    int idx = blockIdx.x * blockDim.x + tid;
    if (idx < N_NODES * FIN) {
        int n = idx / FIN, g = idx % FIN;
        float v = fmaxf(g_h[idx] * sc[g] + bi[g], 0.0f);
        atomicAdd(&g_graph[batch[n] * FIN + g], v);
    }
}

// ---------------- final MLP --------------------------------------------------
__global__ void k_mlp(const float* __restrict__ w1, const float* __restrict__ b1,
                      const float* __restrict__ w2, const float* __restrict__ b2,
                      const float* __restrict__ w3, const float* __restrict__ b3,
                      float* __restrict__ out) {
    __shared__ float row[FIN], t1[50], t2[25];
    int b = blockIdx.x, tid = threadIdx.x;
    if (tid < FIN) row[tid] = g_graph[b * FIN + tid];
    __syncthreads();
    if (tid < 50) {
        float a = b1[tid];
        for (int f = 0; f < FIN; f++) a += row[f] * w1[f * 50 + tid];
        t1[tid] = fmaxf(a, 0.0f);
    }
    __syncthreads();
    if (tid < 25) {
        float a = b2[tid];
        for (int f = 0; f < 50; f++) a += t1[f] * w2[f * 25 + tid];
        t2[tid] = fmaxf(a, 0.0f);
    }
    __syncthreads();
    if (tid == 0) {
        float a = b3[0];
        for (int f = 0; f < 25; f++) a += t2[f] * w3[f];
        out[b] = a;
    }
}

// ---------------- launch -----------------------------------------------------
extern "C" void kernel_launch(void* const* d_in, const int* in_sizes, int n_in,
                              void* d_out, int out_size) {
    const int*   x        = (const int*)d_in[0];
    const int*   ei       = (const int*)d_in[1];
    const int*   ea       = (const int*)d_in[2];
    const int*   batch    = (const int*)d_in[3];
    const float* node_emb = (const float*)d_in[4];
    const float* edge_emb = (const float*)d_in[5];
    const float* encw     = (const float*)d_in[6];
    const float* encb     = (const float*)d_in[7];
    const float* prew     = (const float*)d_in[8];
    const float* preb     = (const float*)d_in[9];
    const float* postw    = (const float*)d_in[10];
    const float* postb    = (const float*)d_in[11];
    const float* linw     = (const float*)d_in[12];
    const float* linb     = (const float*)d_in[13];
    const float* gamma    = (const float*)d_in[14];
    const float* beta     = (const float*)d_in[15];
    const float* w1       = (const float*)d_in[16];
    const float* b1       = (const float*)d_in[17];
    const float* w2       = (const float*)d_in[18];
    const float* b2       = (const float*)d_in[19];
    const float* w3       = (const float*)d_in[20];
    const float* b3       = (const float*)d_in[21];
    float* out = (float*)d_out;

    cudaFuncSetAttribute(k_pre, cudaFuncAttributeMaxDynamicSharedMemorySize,
                         AB_SMEM_FLOATS * (int)sizeof(float));
    cudaFuncSetAttribute(k_ab, cudaFuncAttributeMaxDynamicSharedMemorySize,
                         AB_SMEM_FLOATS * (int)sizeof(float));
    cudaFuncSetAttribute(k_post, cudaFuncAttributeMaxDynamicSharedMemorySize,
                         PB_SMEM_FLOATS * (int)sizeof(float));

    dim3 abgrid(N_NODES / 64, 2);

    // launch slot 4 (the one ncu captures) = k_agg(0)
    k_pre<<<1066, 512, AB_SMEM_FLOATS * (int)sizeof(float)>>>(
        x, ei, node_emb, edge_emb, encw, encb, prew, preb);
    k_scan<<<1, 256>>>();
    k_scatter<<<N_EDGES / 256, 256>>>(ei, ea);

    for (int l = 0; l < NLAYERS; l++) {
        if (l > 0)
            k_ab<<<abgrid, 512, AB_SMEM_FLOATS * (int)sizeof(float)>>>(l, prew, gamma, beta);
        k_agg<<<N_NODES / 4, 384>>>(l);
        k_post<<<N_NODES / PBN, 256, PB_SMEM_FLOATS * (int)sizeof(float)>>>(
            l, postw, postb, linw, linb);
    }

    k_readout<<<(N_NODES * FIN + 255) / 256, 256>>>(batch, gamma, beta);
    k_mlp<<<NGRAPH, 96>>>(w1, b1, w2, b2, w3, b3, out);
}